// round 1
// baseline (speedup 1.0000x reference)
#include <cuda_runtime.h>
#include <math.h>

#define SQ   2640          // sequence length S
#define TF   880           // tokens per frame T
#define NHH  12            // heads
#define HDD  128           // head dim
#define NEL  (SQ*NHH*HDD)  // 4,055,040
#define BM   64
#define BN   64
#define VSTRIDE 132        // padded V row stride in smem (floats)
#define SCALE 0.088388347648318447f  // 1/sqrt(128)

// ---------------- scratch (device globals — no allocation) ----------------
__device__ float g_qr [NHH*SQ*HDD];   // rope Q, [h][s][d], pre-scaled
__device__ float g_krt[NHH*HDD*SQ];   // rope K, [h][d][s] (transposed)
__device__ float g_vt [NHH*SQ*HDD];   // V,      [h][s][d]
__device__ float g_qp [NHH*SQ*HDD];   // prope Q, pre-scaled
__device__ float g_kpt[NHH*HDD*SQ];   // prope K, transposed
__device__ float g_vp [NHH*SQ*HDD];   // prope V
__device__ float g_po [SQ*NHH*HDD];   // prope attention output (pre-projection), [s][h][d]
__device__ float g_P  [3][16];
__device__ float g_Pi [3][16];

// ---------------- kernel 1: P = Kpad @ viewmat, Pinv ----------------
__global__ void mats_kernel(const float* __restrict__ vm, const float* __restrict__ Ks) {
    int f = threadIdx.x;
    if (f >= 3) return;
    float P[16];
    // rows 0..2:  sum_{k<3} Ks[i][k] * vm[k][j];  row 3: vm[3][j]
    for (int i = 0; i < 3; i++)
        for (int j = 0; j < 4; j++) {
            float s = 0.f;
            for (int k2 = 0; k2 < 3; k2++)
                s += Ks[f*9 + i*3 + k2] * vm[f*16 + k2*4 + j];
            P[i*4 + j] = s;
        }
    for (int j = 0; j < 4; j++) P[12 + j] = vm[f*16 + 12 + j];
    for (int i = 0; i < 16; i++) g_P[f][i] = P[i];

    // Gauss-Jordan inverse with partial pivoting (double internally)
    double M[4][8];
    for (int i = 0; i < 4; i++)
        for (int j = 0; j < 4; j++) {
            M[i][j]     = (double)P[i*4 + j];
            M[i][4 + j] = (i == j) ? 1.0 : 0.0;
        }
    for (int col = 0; col < 4; col++) {
        int piv = col; double best = fabs(M[col][col]);
        for (int r = col + 1; r < 4; r++)
            if (fabs(M[r][col]) > best) { best = fabs(M[r][col]); piv = r; }
        if (piv != col)
            for (int j = 0; j < 8; j++) { double t = M[col][j]; M[col][j] = M[piv][j]; M[piv][j] = t; }
        double inv = 1.0 / M[col][col];
        for (int j = 0; j < 8; j++) M[col][j] *= inv;
        for (int r = 0; r < 4; r++) {
            if (r == col) continue;
            double fm = M[r][col];
            for (int j = 0; j < 8; j++) M[r][j] -= fm * M[col][j];
        }
    }
    for (int i = 0; i < 4; i++)
        for (int j = 0; j < 4; j++)
            g_Pi[f][i*4 + j] = (float)M[i][4 + j];
}

// ---------------- kernel 2: RoPE + projective transforms ----------------
// grid (SQ, NHH), block 128
__global__ void preproc_kernel(const float* __restrict__ q, const float* __restrict__ k,
                               const float* __restrict__ v, const float* __restrict__ cosb,
                               const float* __restrict__ sinb) {
    int s = blockIdx.x, h = blockIdx.y, t = threadIdx.x;
    int f = s / TF;
    __shared__ float qs[HDD], ks[HDD], vs[HDD];
    int base = (s*NHH + h)*HDD;
    qs[t] = q[base + t];
    ks[t] = k[base + t];
    vs[t] = v[base + t];
    __syncthreads();

    // RoPE (interleaved pairs)
    int i = t >> 1;
    float c  = cosb[s*64 + i];
    float sn = sinb[s*64 + i];
    float x1q = qs[2*i], x2q = qs[2*i + 1];
    float x1k = ks[2*i], x2k = ks[2*i + 1];
    float qr, kr;
    if ((t & 1) == 0) { qr = x1q*c - x2q*sn; kr = x1k*c - x2k*sn; }
    else              { qr = x2q*c + x1q*sn; kr = x2k*c + x1k*sn; }

    // projective: 4-vector transforms
    int r = t & 3, g4 = t & ~3;
    const float* P  = g_P[f];
    const float* Pi = g_Pi[f];
    float qp = 0.f, kp = 0.f, vp = 0.f;
    #pragma unroll
    for (int c2 = 0; c2 < 4; c2++) {
        qp += P [r*4 + c2] * qs[g4 + c2];   // P  @ q
        kp += Pi[c2*4 + r] * ks[g4 + c2];   // Pinv^T @ k
        vp += Pi[r*4 + c2] * vs[g4 + c2];   // Pinv @ v
    }
    int hs = (h*SQ + s)*HDD + t;
    int ht = (h*HDD + t)*SQ + s;
    g_qr [hs] = qr * SCALE;
    g_krt[ht] = kr;
    g_vt [hs] = vs[t];
    g_qp [hs] = qp * SCALE;
    g_kpt[ht] = kp;
    g_vp [hs] = vp;
}

// ---------------- kernel 3: flash attention (both kinds) ----------------
// grid (42, 12, 2), block 256, dynamic smem
__global__ __launch_bounds__(256) void attn_kernel(float* __restrict__ out0) {
    extern __shared__ float sm[];
    float* sQ   = sm;                        // BM * HDD
    float* sKV  = sm + BM*HDD;               // max(HDD*BN, BN*VSTRIDE) = BN*VSTRIDE
    float* sP   = sKV + BN*VSTRIDE;          // BM * BN
    float* sAux = sP + BM*BN;                // BM

    int kind = blockIdx.z;
    int h    = blockIdx.y;
    int row0 = blockIdx.x * BM;

    const float* Q  = (kind ? g_qp  : g_qr ) + h*SQ*HDD;
    const float* Kt = (kind ? g_kpt : g_krt) + h*HDD*SQ;
    const float* V  = (kind ? g_vp  : g_vt ) + h*SQ*HDD;
    float* Out = kind ? g_po : out0;   // both [s][h][d]

    int tid = threadIdx.x;
    int ty = tid >> 4, tx = tid & 15;

    // load Q tile [BM][HDD]
    for (int idx = tid; idx < BM*(HDD/4); idx += 256) {
        int r = idx >> 5, c4 = (idx & 31) << 2;
        float4 val = make_float4(0.f, 0.f, 0.f, 0.f);
        int srow = row0 + r;
        if (srow < SQ) val = *(const float4*)(Q + srow*HDD + c4);
        *(float4*)(sQ + r*HDD + c4) = val;
    }

    float accO[4][8];
    #pragma unroll
    for (int i = 0; i < 4; i++)
        #pragma unroll
        for (int j = 0; j < 8; j++) accO[i][j] = 0.f;

    float m_r = -1e30f, l_r = 0.f;  // row state, valid for tid < BM

    int rowlast = min(row0 + BM - 1, SQ - 1);
    int kend = min(SQ, (rowlast/TF + 1)*TF);

    for (int j0 = 0; j0 < kend; j0 += BN) {
        __syncthreads();  // protect sKV (prev V) and sQ on first iter

        // load K tile transposed: sKt[k][col], stride BN
        for (int idx = tid; idx < HDD*(BN/4); idx += 256) {
            int kk = idx >> 4, c4 = (idx & 15) << 2;
            int tcol = j0 + c4;
            float4 val = make_float4(0.f, 0.f, 0.f, 0.f);
            if (tcol < SQ) val = *(const float4*)(Kt + kk*SQ + tcol);
            *(float4*)(sKV + kk*BN + c4) = val;
        }
        __syncthreads();

        // scores: 4x4 microtile per thread
        float acc[4][4];
        #pragma unroll
        for (int i = 0; i < 4; i++)
            #pragma unroll
            for (int j = 0; j < 4; j++) acc[i][j] = 0.f;

        #pragma unroll 4
        for (int kk = 0; kk < HDD; kk += 4) {
            float4 qv[4], kv[4];
            #pragma unroll
            for (int i = 0; i < 4; i++) qv[i] = *(const float4*)(sQ + (4*ty + i)*HDD + kk);
            #pragma unroll
            for (int u = 0; u < 4; u++) kv[u] = *(const float4*)(sKV + (kk + u)*BN + 4*tx);
            #pragma unroll
            for (int i = 0; i < 4; i++) {
                acc[i][0] += qv[i].x*kv[0].x + qv[i].y*kv[1].x + qv[i].z*kv[2].x + qv[i].w*kv[3].x;
                acc[i][1] += qv[i].x*kv[0].y + qv[i].y*kv[1].y + qv[i].z*kv[2].y + qv[i].w*kv[3].y;
                acc[i][2] += qv[i].x*kv[0].z + qv[i].y*kv[1].z + qv[i].z*kv[2].z + qv[i].w*kv[3].z;
                acc[i][3] += qv[i].x*kv[0].w + qv[i].y*kv[1].w + qv[i].z*kv[2].w + qv[i].w*kv[3].w;
            }
        }

        // mask + store scores
        #pragma unroll
        for (int i = 0; i < 4; i++) {
            int srow = row0 + 4*ty + i;
            int km = (srow/TF + 1)*TF;
            #pragma unroll
            for (int j = 0; j < 4; j++) {
                int tcol = j0 + 4*tx + j;
                float sc = acc[i][j];
                if (tcol >= km || tcol >= SQ) sc = -1e30f;
                sP[(4*ty + i)*BN + 4*tx + j] = sc;
            }
        }
        __syncthreads();

        // tid<BM: online softmax for one row; others: load V tile
        if (tid < BM) {
            int r = tid;
            float mm = m_r;
            #pragma unroll 8
            for (int c = 0; c < BN; c++) mm = fmaxf(mm, sP[r*BN + c]);
            float al = __expf(m_r - mm);
            float ps = 0.f;
            #pragma unroll 8
            for (int c = 0; c < BN; c++) {
                float p = __expf(sP[r*BN + c] - mm);
                sP[r*BN + c] = p;
                ps += p;
            }
            l_r = l_r*al + ps;
            m_r = mm;
            sAux[r] = al;
        } else {
            for (int idx = tid - BM; idx < BN*(HDD/4); idx += 256 - BM) {
                int col = idx >> 5, c4 = (idx & 31) << 2;
                int tcol = j0 + col;
                float4 val = make_float4(0.f, 0.f, 0.f, 0.f);
                if (tcol < SQ) val = *(const float4*)(V + tcol*HDD + c4);
                *(float4*)(sKV + col*VSTRIDE + c4) = val;
            }
        }
        __syncthreads();

        // rescale + P@V
        float al[4];
        #pragma unroll
        for (int i = 0; i < 4; i++) al[i] = sAux[4*ty + i];
        #pragma unroll
        for (int i = 0; i < 4; i++)
            #pragma unroll
            for (int j = 0; j < 8; j++) accO[i][j] *= al[i];

        #pragma unroll 2
        for (int col = 0; col < BN; col++) {
            float p[4];
            #pragma unroll
            for (int i = 0; i < 4; i++) p[i] = sP[(4*ty + i)*BN + col];
            float4 va = *(const float4*)(sKV + col*VSTRIDE + 8*tx);
            float4 vb = *(const float4*)(sKV + col*VSTRIDE + 8*tx + 4);
            #pragma unroll
            for (int i = 0; i < 4; i++) {
                accO[i][0] += p[i]*va.x;  accO[i][1] += p[i]*va.y;
                accO[i][2] += p[i]*va.z;  accO[i][3] += p[i]*va.w;
                accO[i][4] += p[i]*vb.x;  accO[i][5] += p[i]*vb.y;
                accO[i][6] += p[i]*vb.z;  accO[i][7] += p[i]*vb.w;
            }
        }
    }

    // epilogue: normalize and write
    __syncthreads();
    if (tid < BM) sAux[tid] = l_r;
    __syncthreads();
    #pragma unroll
    for (int i = 0; i < 4; i++) {
        int srow = row0 + 4*ty + i;
        if (srow < SQ) {
            float linv = 1.f / sAux[4*ty + i];
            float4 o0 = make_float4(accO[i][0]*linv, accO[i][1]*linv, accO[i][2]*linv, accO[i][3]*linv);
            float4 o1 = make_float4(accO[i][4]*linv, accO[i][5]*linv, accO[i][6]*linv, accO[i][7]*linv);
            float* dst = Out + srow*(NHH*HDD) + h*HDD + 8*tx;
            *(float4*)(dst)     = o0;
            *(float4*)(dst + 4) = o1;
        }
    }
}

// ---------------- kernel 4: final projection of prope output ----------------
__global__ void proj_out_kernel(float* __restrict__ out1) {
    int idx4 = blockIdx.x*blockDim.x + threadIdx.x;
    if (idx4 >= NEL/4) return;
    int idx = idx4 << 2;
    int s = idx / (NHH*HDD);
    int f = s / TF;
    const float* P = g_P[f];
    float4 po = *(const float4*)(g_po + idx);
    float4 o;
    o.x = P[0]*po.x  + P[1]*po.y  + P[2]*po.z  + P[3]*po.w;
    o.y = P[4]*po.x  + P[5]*po.y  + P[6]*po.z  + P[7]*po.w;
    o.z = P[8]*po.x  + P[9]*po.y  + P[10]*po.z + P[11]*po.w;
    o.w = P[12]*po.x + P[13]*po.y + P[14]*po.z + P[15]*po.w;
    *(float4*)(out1 + idx) = o;
}

// ---------------- launch ----------------
extern "C" void kernel_launch(void* const* d_in, const int* in_sizes, int n_in,
                              void* d_out, int out_size) {
    const float* q    = (const float*)d_in[0];
    const float* k    = (const float*)d_in[1];
    const float* v    = (const float*)d_in[2];
    const float* cosb = (const float*)d_in[3];
    const float* sinb = (const float*)d_in[4];
    const float* vm   = (const float*)d_in[5];
    const float* Ks   = (const float*)d_in[6];
    float* out = (float*)d_out;

    const int smem_bytes = (BM*HDD + BN*VSTRIDE + BM*BN + BM) * sizeof(float); // 83,200 B
    cudaFuncSetAttribute(attn_kernel, cudaFuncAttributeMaxDynamicSharedMemorySize, smem_bytes);

    mats_kernel<<<1, 32>>>(vm, Ks);
    preproc_kernel<<<dim3(SQ, NHH), 128>>>(q, k, v, cosb, sinb);
    attn_kernel<<<dim3((SQ + BM - 1)/BM, NHH, 2), 256, smem_bytes>>>(out);
    proj_out_kernel<<<(NEL/4 + 255)/256, 256>>>(out + NEL);
}

// round 3
// speedup vs baseline: 3.7138x; 3.7138x over previous
#include <cuda_runtime.h>
#include <math.h>

#define SQ   2640
#define TF   880
#define NHH  12
#define HDD  128
#define NEL  (SQ*NHH*HDD)
#define SCALE 0.088388347648318447f

#define BM 64
#define BN 64
#define KSTR 132
#define PSTR 68

__device__ float g_qr[NHH*SQ*HDD];
__device__ float g_kr[NHH*SQ*HDD];
__device__ float g_qp[NHH*SQ*HDD];
__device__ float g_kp[NHH*SQ*HDD];
__device__ float g_vp[NHH*SQ*HDD];
__device__ float g_po[SQ*NHH*HDD];
__device__ float g_P [3][16];
__device__ float g_Pi[3][16];

__device__ __forceinline__ float to_tf32(float x) {
    unsigned u;
    asm("cvt.rna.tf32.f32 %0, %1;" : "=r"(u) : "f"(x));
    return __uint_as_float(u);
}

#define MMA_TF32(D, A, b0, b1)                                              \
  asm volatile("mma.sync.aligned.m16n8k8.row.col.f32.tf32.tf32.f32 "        \
    "{%0,%1,%2,%3},{%4,%5,%6,%7},{%8,%9},{%0,%1,%2,%3};"                    \
    : "+f"((D)[0]), "+f"((D)[1]), "+f"((D)[2]), "+f"((D)[3])                \
    : "r"(__float_as_uint((A)[0])), "r"(__float_as_uint((A)[1])),           \
      "r"(__float_as_uint((A)[2])), "r"(__float_as_uint((A)[3])),           \
      "r"(__float_as_uint(b0)), "r"(__float_as_uint(b1)))

__global__ void mats_kernel(const float* __restrict__ vm, const float* __restrict__ Ks) {
    int f = threadIdx.x;
    if (f >= 3) return;
    float P[16];
    for (int i = 0; i < 3; i++)
        for (int j = 0; j < 4; j++) {
            float s = 0.f;
            for (int k2 = 0; k2 < 3; k2++)
                s += Ks[f*9 + i*3 + k2] * vm[f*16 + k2*4 + j];
            P[i*4 + j] = s;
        }
    for (int j = 0; j < 4; j++) P[12 + j] = vm[f*16 + 12 + j];
    for (int i = 0; i < 16; i++) g_P[f][i] = P[i];

    double M[4][8];
    for (int i = 0; i < 4; i++)
        for (int j = 0; j < 4; j++) {
            M[i][j]     = (double)P[i*4 + j];
            M[i][4 + j] = (i == j) ? 1.0 : 0.0;
        }
    for (int col = 0; col < 4; col++) {
        int piv = col; double best = fabs(M[col][col]);
        for (int r = col + 1; r < 4; r++)
            if (fabs(M[r][col]) > best) { best = fabs(M[r][col]); piv = r; }
        if (piv != col)
            for (int j = 0; j < 8; j++) { double t = M[col][j]; M[col][j] = M[piv][j]; M[piv][j] = t; }
        double inv = 1.0 / M[col][col];
        for (int j = 0; j < 8; j++) M[col][j] *= inv;
        for (int r = 0; r < 4; r++) {
            if (r == col) continue;
            double fm = M[r][col];
            for (int j = 0; j < 8; j++) M[r][j] -= fm * M[col][j];
        }
    }
    for (int i = 0; i < 4; i++)
        for (int j = 0; j < 4; j++)
            g_Pi[f][i*4 + j] = (float)M[i][4 + j];
}

__global__ void preproc_kernel(const float4* __restrict__ q, const float4* __restrict__ k,
                               const float4* __restrict__ v, const float* __restrict__ cosb,
                               const float* __restrict__ sinb) {
    int t = blockIdx.x*blockDim.x + threadIdx.x;
    if (t >= SQ*NHH*32) return;
    int d4 = t & 31;
    int h  = (t >> 5) % NHH;
    int s  = t / (NHH*32);
    int f  = s / TF;

    float4 q4 = q[(s*NHH + h)*32 + d4];
    float4 k4 = k[(s*NHH + h)*32 + d4];
    float4 v4 = v[(s*NHH + h)*32 + d4];
    float c0 = cosb[s*64 + 2*d4], c1 = cosb[s*64 + 2*d4 + 1];
    float s0 = sinb[s*64 + 2*d4], s1 = sinb[s*64 + 2*d4 + 1];

    float4 qr, kr;
    qr.x = (q4.x*c0 - q4.y*s0)*SCALE; qr.y = (q4.y*c0 + q4.x*s0)*SCALE;
    qr.z = (q4.z*c1 - q4.w*s1)*SCALE; qr.w = (q4.w*c1 + q4.z*s1)*SCALE;
    kr.x = k4.x*c0 - k4.y*s0;         kr.y = k4.y*c0 + k4.x*s0;
    kr.z = k4.z*c1 - k4.w*s1;         kr.w = k4.w*c1 + k4.z*s1;

    const float* P  = g_P[f];
    const float* Pi = g_Pi[f];
    float4 qp, kp, vp;
    qp.x = (P[0] *q4.x + P[1] *q4.y + P[2] *q4.z + P[3] *q4.w)*SCALE;
    qp.y = (P[4] *q4.x + P[5] *q4.y + P[6] *q4.z + P[7] *q4.w)*SCALE;
    qp.z = (P[8] *q4.x + P[9] *q4.y + P[10]*q4.z + P[11]*q4.w)*SCALE;
    qp.w = (P[12]*q4.x + P[13]*q4.y + P[14]*q4.z + P[15]*q4.w)*SCALE;
    kp.x = Pi[0]*k4.x + Pi[4]*k4.y + Pi[8] *k4.z + Pi[12]*k4.w;
    kp.y = Pi[1]*k4.x + Pi[5]*k4.y + Pi[9] *k4.z + Pi[13]*k4.w;
    kp.z = Pi[2]*k4.x + Pi[6]*k4.y + Pi[10]*k4.z + Pi[14]*k4.w;
    kp.w = Pi[3]*k4.x + Pi[7]*k4.y + Pi[11]*k4.z + Pi[15]*k4.w;
    vp.x = Pi[0] *v4.x + Pi[1] *v4.y + Pi[2] *v4.z + Pi[3] *v4.w;
    vp.y = Pi[4] *v4.x + Pi[5] *v4.y + Pi[6] *v4.z + Pi[7] *v4.w;
    vp.z = Pi[8] *v4.x + Pi[9] *v4.y + Pi[10]*v4.z + Pi[11]*v4.w;
    vp.w = Pi[12]*v4.x + Pi[13]*v4.y + Pi[14]*v4.z + Pi[15]*v4.w;

    qr.x = to_tf32(qr.x); qr.y = to_tf32(qr.y); qr.z = to_tf32(qr.z); qr.w = to_tf32(qr.w);
    kr.x = to_tf32(kr.x); kr.y = to_tf32(kr.y); kr.z = to_tf32(kr.z); kr.w = to_tf32(kr.w);
    qp.x = to_tf32(qp.x); qp.y = to_tf32(qp.y); qp.z = to_tf32(qp.z); qp.w = to_tf32(qp.w);
    kp.x = to_tf32(kp.x); kp.y = to_tf32(kp.y); kp.z = to_tf32(kp.z); kp.w = to_tf32(kp.w);
    vp.x = to_tf32(vp.x); vp.y = to_tf32(vp.y); vp.z = to_tf32(vp.z); vp.w = to_tf32(vp.w);

    int o = (h*SQ + s)*32 + d4;
    ((float4*)g_qr)[o] = qr;
    ((float4*)g_kr)[o] = kr;
    ((float4*)g_qp)[o] = qp;
    ((float4*)g_kp)[o] = kp;
    ((float4*)g_vp)[o] = vp;
}

__global__ __launch_bounds__(128, 2) void attn_kernel(const float* __restrict__ vin,
                                                      float* __restrict__ out0) {
    extern __shared__ float sm[];
    float* sK = sm;
    float* sV = sK + BN*KSTR;
    float* sPb = sV + BN*KSTR;

    int kind = blockIdx.z, h = blockIdx.y;
    int row0 = blockIdx.x * BM;
    int tid = threadIdx.x;
    int w = tid >> 5, lane = tid & 31, g = lane >> 2, a = lane & 3;

    float* sP = sPb + w*16*PSTR;   // warp-private 16 rows

    const float* Q = (kind ? g_qp : g_qr) + h*SQ*HDD;
    const float* K = (kind ? g_kp : g_kr) + h*SQ*HDD;
    const float* Vb; int vstr;
    if (kind) { Vb = g_vp + h*SQ*HDD; vstr = HDD; }
    else      { Vb = vin  + h*HDD;    vstr = NHH*HDD; }
    float* Out = kind ? g_po : out0;

    int rw  = row0 + w*16;
    int ra  = rw + g, rb = rw + g + 8;
    int rca = min(ra, SQ-1), rcb = min(rb, SQ-1);
    int kma = (rca/TF + 1)*TF;
    int kmb = (rcb/TF + 1)*TF;

    float qf[16][4];
    {
        const float* Qa = Q + rca*HDD;
        const float* Qb = Q + rcb*HDD;
        #pragma unroll
        for (int ks = 0; ks < 16; ks++) {
            qf[ks][0] = Qa[8*ks + a];
            qf[ks][1] = Qb[8*ks + a];
            qf[ks][2] = Qa[8*ks + a + 4];
            qf[ks][3] = Qb[8*ks + a + 4];
        }
    }

    float of[16][4];
    #pragma unroll
    for (int n = 0; n < 16; n++) { of[n][0]=0.f; of[n][1]=0.f; of[n][2]=0.f; of[n][3]=0.f; }
    float m0 = -1e30f, m1 = -1e30f, l0 = 0.f, l1 = 0.f;

    int kend = (min(row0 + BM - 1, SQ-1)/TF + 1)*TF;

    for (int j0 = 0; j0 < kend; j0 += BN) {
        __syncthreads();
        #pragma unroll
        for (int it = 0; it < 16; it++) {
            int idx = tid + it*128;
            int col = idx >> 5;
            int c4  = (idx & 31) << 2;
            int gc  = min(j0 + col, SQ-1);
            float4 kv = *(const float4*)(K  + gc*HDD  + c4);
            float4 vv = *(const float4*)(Vb + gc*vstr + c4);
            *(float4*)(sK + col*KSTR + c4) = kv;
            *(float4*)(sV + col*KSTR + c4) = vv;
        }
        __syncthreads();

        float sf[8][4];
        #pragma unroll
        for (int n = 0; n < 8; n++) { sf[n][0]=0.f; sf[n][1]=0.f; sf[n][2]=0.f; sf[n][3]=0.f; }

        #pragma unroll
        for (int ks = 0; ks < 16; ks++) {
            #pragma unroll
            for (int n = 0; n < 8; n++) {
                float b0 = sK[(n*8 + g)*KSTR + 8*ks + a];
                float b1 = sK[(n*8 + g)*KSTR + 8*ks + a + 4];
                MMA_TF32(sf[n], qf[ks], b0, b1);
            }
        }

        #pragma unroll
        for (int n = 0; n < 8; n++) {
            int c0 = j0 + n*8 + 2*a;
            if (c0     >= kma) sf[n][0] = -1e30f;
            if (c0 + 1 >= kma) sf[n][1] = -1e30f;
            if (c0     >= kmb) sf[n][2] = -1e30f;
            if (c0 + 1 >= kmb) sf[n][3] = -1e30f;
        }

        float mx0 = -1e30f, mx1 = -1e30f;
        #pragma unroll
        for (int n = 0; n < 8; n++) {
            mx0 = fmaxf(mx0, fmaxf(sf[n][0], sf[n][1]));
            mx1 = fmaxf(mx1, fmaxf(sf[n][2], sf[n][3]));
        }
        mx0 = fmaxf(mx0, __shfl_xor_sync(0xffffffffu, mx0, 1));
        mx0 = fmaxf(mx0, __shfl_xor_sync(0xffffffffu, mx0, 2));
        mx1 = fmaxf(mx1, __shfl_xor_sync(0xffffffffu, mx1, 1));
        mx1 = fmaxf(mx1, __shfl_xor_sync(0xffffffffu, mx1, 2));

        float mn0 = fmaxf(m0, mx0), mn1 = fmaxf(m1, mx1);
        float al0 = __expf(m0 - mn0), al1 = __expf(m1 - mn1);
        float ps0 = 0.f, ps1 = 0.f;
        #pragma unroll
        for (int n = 0; n < 8; n++) {
            float p00 = to_tf32(__expf(sf[n][0] - mn0));
            float p01 = to_tf32(__expf(sf[n][1] - mn0));
            float p10 = to_tf32(__expf(sf[n][2] - mn1));
            float p11 = to_tf32(__expf(sf[n][3] - mn1));
            ps0 += p00 + p01;
            ps1 += p10 + p11;
            *(float2*)(sP + g*PSTR     + n*8 + 2*a) = make_float2(p00, p01);
            *(float2*)(sP + (g+8)*PSTR + n*8 + 2*a) = make_float2(p10, p11);
        }
        ps0 += __shfl_xor_sync(0xffffffffu, ps0, 1);
        ps0 += __shfl_xor_sync(0xffffffffu, ps0, 2);
        ps1 += __shfl_xor_sync(0xffffffffu, ps1, 1);
        ps1 += __shfl_xor_sync(0xffffffffu, ps1, 2);
        l0 = l0*al0 + ps0;  l1 = l1*al1 + ps1;
        m0 = mn0;           m1 = mn1;

        #pragma unroll
        for (int n = 0; n < 16; n++) {
            of[n][0] *= al0; of[n][1] *= al0;
            of[n][2] *= al1; of[n][3] *= al1;
        }

        #pragma unroll
        for (int ks = 0; ks < 8; ks++) {
            float pa[4];
            pa[0] = sP[g*PSTR     + 8*ks + a];
            pa[1] = sP[(g+8)*PSTR + 8*ks + a];
            pa[2] = sP[g*PSTR     + 8*ks + a + 4];
            pa[3] = sP[(g+8)*PSTR + 8*ks + a + 4];
            #pragma unroll
            for (int n = 0; n < 16; n++) {
                float b0 = sV[(8*ks + a)*KSTR     + n*8 + g];
                float b1 = sV[(8*ks + a + 4)*KSTR + n*8 + g];
                MMA_TF32(of[n], pa, b0, b1);
            }
        }
    }

    float li0 = 1.f / l0, li1 = 1.f / l1;
    if (ra < SQ) {
        float* da = Out + ra*(NHH*HDD) + h*HDD;
        #pragma unroll
        for (int n = 0; n < 16; n++)
            *(float2*)(da + n*8 + 2*a) = make_float2(of[n][0]*li0, of[n][1]*li0);
    }
    if (rb < SQ) {
        float* db = Out + rb*(NHH*HDD) + h*HDD;
        #pragma unroll
        for (int n = 0; n < 16; n++)
            *(float2*)(db + n*8 + 2*a) = make_float2(of[n][2]*li1, of[n][3]*li1);
    }
}

__global__ void proj_out_kernel(float* __restrict__ out1) {
    int idx4 = blockIdx.x*blockDim.x + threadIdx.x;
    if (idx4 >= NEL/4) return;
    int idx = idx4 << 2;
    int s = idx / (NHH*HDD);
    int f = s / TF;
    const float* P = g_P[f];
    float4 po = *(const float4*)(g_po + idx);
    float4 o;
    o.x = P[0] *po.x + P[1] *po.y + P[2] *po.z + P[3] *po.w;
    o.y = P[4] *po.x + P[5] *po.y + P[6] *po.z + P[7] *po.w;
    o.z = P[8] *po.x + P[9] *po.y + P[10]*po.z + P[11]*po.w;
    o.w = P[12]*po.x + P[13]*po.y + P[14]*po.z + P[15]*po.w;
    *(float4*)(out1 + idx) = o;
}

extern "C" void kernel_launch(void* const* d_in, const int* in_sizes, int n_in,
                              void* d_out, int out_size) {
    const float* q    = (const float*)d_in[0];
    const float* k    = (const float*)d_in[1];
    const float* v    = (const float*)d_in[2];
    const float* cosb = (const float*)d_in[3];
    const float* sinb = (const float*)d_in[4];
    const float* vm   = (const float*)d_in[5];
    const float* Ks   = (const float*)d_in[6];
    float* out = (float*)d_out;

    const int smem_bytes = (2*BN*KSTR + BM*PSTR) * sizeof(float);  // 84,992 B
    cudaFuncSetAttribute(attn_kernel, cudaFuncAttributeMaxDynamicSharedMemorySize, smem_bytes);

    mats_kernel<<<1, 32>>>(vm, Ks);
    preproc_kernel<<<(SQ*NHH*32 + 255)/256, 256>>>((const float4*)q, (const float4*)k,
                                                   (const float4*)v, cosb, sinb);
    attn_kernel<<<dim3((SQ + BM - 1)/BM, NHH, 2), 128, smem_bytes>>>(v, out);
    proj_out_kernel<<<(NEL/4 + 255)/256, 256>>>(out + NEL);
}

// round 4
// speedup vs baseline: 3.8303x; 1.0314x over previous
#include <cuda_runtime.h>
#include <math.h>

#define SQ   2640
#define TF   880
#define NHH  12
#define HDD  128
#define NEL  (SQ*NHH*HDD)
#define SCALE 0.088388347648318447f

#define BM 128
#define BN 64
#define KSTR 132
#define PSTR 68
#define STAGEF (2*BN*KSTR)          // floats per stage (K tile + V tile)
#define TILEF  (BN*KSTR)            // floats per K (or V) tile

__device__ float g_qr[NHH*SQ*HDD];
__device__ float g_kr[NHH*SQ*HDD];
__device__ float g_qp[NHH*SQ*HDD];
__device__ float g_kp[NHH*SQ*HDD];
__device__ float g_vp[NHH*SQ*HDD];
__device__ float g_po[SQ*NHH*HDD];
__device__ float g_P [3][16];
__device__ float g_Pi[3][16];

__device__ __forceinline__ float to_tf32(float x) {
    unsigned u;
    asm("cvt.rna.tf32.f32 %0, %1;" : "=r"(u) : "f"(x));
    return __uint_as_float(u);
}

__device__ __forceinline__ void cp_async16(unsigned dst, const void* src) {
    asm volatile("cp.async.cg.shared.global [%0], [%1], 16;" :: "r"(dst), "l"(src));
}

#define MMA_TF32(D, A, b0, b1)                                              \
  asm volatile("mma.sync.aligned.m16n8k8.row.col.f32.tf32.tf32.f32 "        \
    "{%0,%1,%2,%3},{%4,%5,%6,%7},{%8,%9},{%0,%1,%2,%3};"                    \
    : "+f"((D)[0]), "+f"((D)[1]), "+f"((D)[2]), "+f"((D)[3])                \
    : "r"(__float_as_uint((A)[0])), "r"(__float_as_uint((A)[1])),           \
      "r"(__float_as_uint((A)[2])), "r"(__float_as_uint((A)[3])),           \
      "r"(__float_as_uint(b0)), "r"(__float_as_uint(b1)))

__global__ void mats_kernel(const float* __restrict__ vm, const float* __restrict__ Ks) {
    int f = threadIdx.x;
    if (f >= 3) return;
    float P[16];
    for (int i = 0; i < 3; i++)
        for (int j = 0; j < 4; j++) {
            float s = 0.f;
            for (int k2 = 0; k2 < 3; k2++)
                s += Ks[f*9 + i*3 + k2] * vm[f*16 + k2*4 + j];
            P[i*4 + j] = s;
        }
    for (int j = 0; j < 4; j++) P[12 + j] = vm[f*16 + 12 + j];
    for (int i = 0; i < 16; i++) g_P[f][i] = P[i];

    double M[4][8];
    for (int i = 0; i < 4; i++)
        for (int j = 0; j < 4; j++) {
            M[i][j]     = (double)P[i*4 + j];
            M[i][4 + j] = (i == j) ? 1.0 : 0.0;
        }
    for (int col = 0; col < 4; col++) {
        int piv = col; double best = fabs(M[col][col]);
        for (int r = col + 1; r < 4; r++)
            if (fabs(M[r][col]) > best) { best = fabs(M[r][col]); piv = r; }
        if (piv != col)
            for (int j = 0; j < 8; j++) { double t = M[col][j]; M[col][j] = M[piv][j]; M[piv][j] = t; }
        double inv = 1.0 / M[col][col];
        for (int j = 0; j < 8; j++) M[col][j] *= inv;
        for (int r = 0; r < 4; r++) {
            if (r == col) continue;
            double fm = M[r][col];
            for (int j = 0; j < 8; j++) M[r][j] -= fm * M[col][j];
        }
    }
    for (int i = 0; i < 4; i++)
        for (int j = 0; j < 4; j++)
            g_Pi[f][i*4 + j] = (float)M[i][4 + j];
}

__global__ void preproc_kernel(const float4* __restrict__ q, const float4* __restrict__ k,
                               const float4* __restrict__ v, const float* __restrict__ cosb,
                               const float* __restrict__ sinb) {
    int t = blockIdx.x*blockDim.x + threadIdx.x;
    if (t >= SQ*NHH*32) return;
    int d4 = t & 31;
    int h  = (t >> 5) % NHH;
    int s  = t / (NHH*32);
    int f  = s / TF;

    float4 q4 = q[(s*NHH + h)*32 + d4];
    float4 k4 = k[(s*NHH + h)*32 + d4];
    float4 v4 = v[(s*NHH + h)*32 + d4];
    float c0 = cosb[s*64 + 2*d4], c1 = cosb[s*64 + 2*d4 + 1];
    float s0 = sinb[s*64 + 2*d4], s1 = sinb[s*64 + 2*d4 + 1];

    float4 qr, kr;
    qr.x = (q4.x*c0 - q4.y*s0)*SCALE; qr.y = (q4.y*c0 + q4.x*s0)*SCALE;
    qr.z = (q4.z*c1 - q4.w*s1)*SCALE; qr.w = (q4.w*c1 + q4.z*s1)*SCALE;
    kr.x = k4.x*c0 - k4.y*s0;         kr.y = k4.y*c0 + k4.x*s0;
    kr.z = k4.z*c1 - k4.w*s1;         kr.w = k4.w*c1 + k4.z*s1;

    const float* P  = g_P[f];
    const float* Pi = g_Pi[f];
    float4 qp, kp, vp;
    qp.x = (P[0] *q4.x + P[1] *q4.y + P[2] *q4.z + P[3] *q4.w)*SCALE;
    qp.y = (P[4] *q4.x + P[5] *q4.y + P[6] *q4.z + P[7] *q4.w)*SCALE;
    qp.z = (P[8] *q4.x + P[9] *q4.y + P[10]*q4.z + P[11]*q4.w)*SCALE;
    qp.w = (P[12]*q4.x + P[13]*q4.y + P[14]*q4.z + P[15]*q4.w)*SCALE;
    kp.x = Pi[0]*k4.x + Pi[4]*k4.y + Pi[8] *k4.z + Pi[12]*k4.w;
    kp.y = Pi[1]*k4.x + Pi[5]*k4.y + Pi[9] *k4.z + Pi[13]*k4.w;
    kp.z = Pi[2]*k4.x + Pi[6]*k4.y + Pi[10]*k4.z + Pi[14]*k4.w;
    kp.w = Pi[3]*k4.x + Pi[7]*k4.y + Pi[11]*k4.z + Pi[15]*k4.w;
    vp.x = Pi[0] *v4.x + Pi[1] *v4.y + Pi[2] *v4.z + Pi[3] *v4.w;
    vp.y = Pi[4] *v4.x + Pi[5] *v4.y + Pi[6] *v4.z + Pi[7] *v4.w;
    vp.z = Pi[8] *v4.x + Pi[9] *v4.y + Pi[10]*v4.z + Pi[11]*v4.w;
    vp.w = Pi[12]*v4.x + Pi[13]*v4.y + Pi[14]*v4.z + Pi[15]*v4.w;

    qr.x = to_tf32(qr.x); qr.y = to_tf32(qr.y); qr.z = to_tf32(qr.z); qr.w = to_tf32(qr.w);
    kr.x = to_tf32(kr.x); kr.y = to_tf32(kr.y); kr.z = to_tf32(kr.z); kr.w = to_tf32(kr.w);
    qp.x = to_tf32(qp.x); qp.y = to_tf32(qp.y); qp.z = to_tf32(qp.z); qp.w = to_tf32(qp.w);
    kp.x = to_tf32(kp.x); kp.y = to_tf32(kp.y); kp.z = to_tf32(kp.z); kp.w = to_tf32(kp.w);
    vp.x = to_tf32(vp.x); vp.y = to_tf32(vp.y); vp.z = to_tf32(vp.z); vp.w = to_tf32(vp.w);

    int o = (h*SQ + s)*32 + d4;
    ((float4*)g_qr)[o] = qr;
    ((float4*)g_kr)[o] = kr;
    ((float4*)g_qp)[o] = qp;
    ((float4*)g_kp)[o] = kp;
    ((float4*)g_vp)[o] = vp;
}

__global__ __launch_bounds__(256, 1) void attn_kernel(const float* __restrict__ vin,
                                                      float* __restrict__ out0) {
    extern __shared__ float sm[];
    // [stage0: K(8448) V(8448)][stage1: K V][sP: 128*68]
    float* sPb = sm + 2*STAGEF;

    int kind = blockIdx.z, h = blockIdx.y;
    int row0 = (gridDim.x - 1 - blockIdx.x) * BM;   // longest blocks first
    int tid = threadIdx.x;
    int w = tid >> 5, lane = tid & 31, g = lane >> 2, a = lane & 3;

    unsigned smem_u32 = (unsigned)__cvta_generic_to_shared(sm);
    float* sP = sPb + w*16*PSTR;

    const float* Q = (kind ? g_qp : g_qr) + h*SQ*HDD;
    const float* K = (kind ? g_kp : g_kr) + h*SQ*HDD;
    const float* Vb; int vstr;
    if (kind) { Vb = g_vp + h*SQ*HDD; vstr = HDD; }
    else      { Vb = vin  + h*HDD;    vstr = NHH*HDD; }
    float* Out = kind ? g_po : out0;

    int rw  = row0 + w*16;
    int ra  = rw + g, rb = rw + g + 8;
    int rca = min(ra, SQ-1), rcb = min(rb, SQ-1);
    int kma = (rca/TF + 1)*TF;
    int kmb = (rcb/TF + 1)*TF;

    float qf[16][4];
    {
        const float* Qa = Q + rca*HDD;
        const float* Qb = Q + rcb*HDD;
        #pragma unroll
        for (int ks = 0; ks < 16; ks++) {
            qf[ks][0] = Qa[8*ks + a];
            qf[ks][1] = Qb[8*ks + a];
            qf[ks][2] = Qa[8*ks + a + 4];
            qf[ks][3] = Qb[8*ks + a + 4];
        }
    }

    float of[16][4];
    #pragma unroll
    for (int n = 0; n < 16; n++) { of[n][0]=0.f; of[n][1]=0.f; of[n][2]=0.f; of[n][3]=0.f; }
    float m0 = -1e30f, m1 = -1e30f, l0 = 0.f, l1 = 0.f;

    int kend = (min(row0 + BM - 1, SQ-1)/TF + 1)*TF;

    // ---- cp.async tile loader ----
    auto issue_tile = [&](int j0, int st) {
        unsigned kbase = smem_u32 + (unsigned)(st*STAGEF)*4u;
        unsigned vbase = kbase + (unsigned)TILEF*4u;
        #pragma unroll
        for (int it = 0; it < 8; it++) {
            int idx = tid + it*256;
            int col = idx >> 5;
            int c4  = (idx & 31) << 2;
            int gc  = min(j0 + col, SQ-1);
            cp_async16(kbase + (unsigned)(col*KSTR + c4)*4u, K  + gc*HDD  + c4);
            cp_async16(vbase + (unsigned)(col*KSTR + c4)*4u, Vb + gc*vstr + c4);
        }
    };

    issue_tile(0, 0);
    asm volatile("cp.async.commit_group;");
    issue_tile(BN, 1);
    asm volatile("cp.async.commit_group;");

    int st = 0;
    for (int j0 = 0; j0 < kend; j0 += BN, st ^= 1) {
        asm volatile("cp.async.wait_group 1;");
        __syncthreads();

        const float* sK = sm + st*STAGEF;
        const float* sV = sK + TILEF;

        float sf[8][4];
        #pragma unroll
        for (int n = 0; n < 8; n++) { sf[n][0]=0.f; sf[n][1]=0.f; sf[n][2]=0.f; sf[n][3]=0.f; }

        #pragma unroll
        for (int ks = 0; ks < 16; ks++) {
            #pragma unroll
            for (int n = 0; n < 8; n++) {
                float b0 = sK[(n*8 + g)*KSTR + 8*ks + a];
                float b1 = sK[(n*8 + g)*KSTR + 8*ks + a + 4];
                MMA_TF32(sf[n], qf[ks], b0, b1);
            }
        }

        #pragma unroll
        for (int n = 0; n < 8; n++) {
            int c0 = j0 + n*8 + 2*a;
            if (c0     >= kma) sf[n][0] = -1e30f;
            if (c0 + 1 >= kma) sf[n][1] = -1e30f;
            if (c0     >= kmb) sf[n][2] = -1e30f;
            if (c0 + 1 >= kmb) sf[n][3] = -1e30f;
        }

        float mx0 = -1e30f, mx1 = -1e30f;
        #pragma unroll
        for (int n = 0; n < 8; n++) {
            mx0 = fmaxf(mx0, fmaxf(sf[n][0], sf[n][1]));
            mx1 = fmaxf(mx1, fmaxf(sf[n][2], sf[n][3]));
        }
        mx0 = fmaxf(mx0, __shfl_xor_sync(0xffffffffu, mx0, 1));
        mx0 = fmaxf(mx0, __shfl_xor_sync(0xffffffffu, mx0, 2));
        mx1 = fmaxf(mx1, __shfl_xor_sync(0xffffffffu, mx1, 1));
        mx1 = fmaxf(mx1, __shfl_xor_sync(0xffffffffu, mx1, 2));

        float mn0 = fmaxf(m0, mx0), mn1 = fmaxf(m1, mx1);
        float al0 = __expf(m0 - mn0), al1 = __expf(m1 - mn1);
        float ps0 = 0.f, ps1 = 0.f;
        #pragma unroll
        for (int n = 0; n < 8; n++) {
            float p00 = to_tf32(__expf(sf[n][0] - mn0));
            float p01 = to_tf32(__expf(sf[n][1] - mn0));
            float p10 = to_tf32(__expf(sf[n][2] - mn1));
            float p11 = to_tf32(__expf(sf[n][3] - mn1));
            ps0 += p00 + p01;
            ps1 += p10 + p11;
            *(float2*)(sP + g*PSTR     + n*8 + 2*a) = make_float2(p00, p01);
            *(float2*)(sP + (g+8)*PSTR + n*8 + 2*a) = make_float2(p10, p11);
        }
        ps0 += __shfl_xor_sync(0xffffffffu, ps0, 1);
        ps0 += __shfl_xor_sync(0xffffffffu, ps0, 2);
        ps1 += __shfl_xor_sync(0xffffffffu, ps1, 1);
        ps1 += __shfl_xor_sync(0xffffffffu, ps1, 2);
        l0 = l0*al0 + ps0;  l1 = l1*al1 + ps1;
        m0 = mn0;           m1 = mn1;

        #pragma unroll
        for (int n = 0; n < 16; n++) {
            of[n][0] *= al0; of[n][1] *= al0;
            of[n][2] *= al1; of[n][3] *= al1;
        }

        #pragma unroll
        for (int ks = 0; ks < 8; ks++) {
            float pa[4];
            pa[0] = sP[g*PSTR     + 8*ks + a];
            pa[1] = sP[(g+8)*PSTR + 8*ks + a];
            pa[2] = sP[g*PSTR     + 8*ks + a + 4];
            pa[3] = sP[(g+8)*PSTR + 8*ks + a + 4];
            #pragma unroll
            for (int n = 0; n < 16; n++) {
                float b0 = sV[(8*ks + a)*KSTR     + n*8 + g];
                float b1 = sV[(8*ks + a + 4)*KSTR + n*8 + g];
                MMA_TF32(of[n], pa, b0, b1);
            }
        }

        __syncthreads();              // everyone done with stage st
        int jn = j0 + 2*BN;
        if (jn < kend) issue_tile(jn, st);
        asm volatile("cp.async.commit_group;");   // commit (possibly empty) to keep counts aligned
    }

    float li0 = 1.f / l0, li1 = 1.f / l1;
    if (ra < SQ) {
        float* da = Out + ra*(NHH*HDD) + h*HDD;
        #pragma unroll
        for (int n = 0; n < 16; n++)
            *(float2*)(da + n*8 + 2*a) = make_float2(of[n][0]*li0, of[n][1]*li0);
    }
    if (rb < SQ) {
        float* db = Out + rb*(NHH*HDD) + h*HDD;
        #pragma unroll
        for (int n = 0; n < 16; n++)
            *(float2*)(db + n*8 + 2*a) = make_float2(of[n][2]*li1, of[n][3]*li1);
    }
}

__global__ void proj_out_kernel(float* __restrict__ out1) {
    int idx4 = blockIdx.x*blockDim.x + threadIdx.x;
    if (idx4 >= NEL/4) return;
    int idx = idx4 << 2;
    int s = idx / (NHH*HDD);
    int f = s / TF;
    const float* P = g_P[f];
    float4 po = *(const float4*)(g_po + idx);
    float4 o;
    o.x = P[0] *po.x + P[1] *po.y + P[2] *po.z + P[3] *po.w;
    o.y = P[4] *po.x + P[5] *po.y + P[6] *po.z + P[7] *po.w;
    o.z = P[8] *po.x + P[9] *po.y + P[10]*po.z + P[11]*po.w;
    o.w = P[12]*po.x + P[13]*po.y + P[14]*po.z + P[15]*po.w;
    *(float4*)(out1 + idx) = o;
}

extern "C" void kernel_launch(void* const* d_in, const int* in_sizes, int n_in,
                              void* d_out, int out_size) {
    const float* q    = (const float*)d_in[0];
    const float* k    = (const float*)d_in[1];
    const float* v    = (const float*)d_in[2];
    const float* cosb = (const float*)d_in[3];
    const float* sinb = (const float*)d_in[4];
    const float* vm   = (const float*)d_in[5];
    const float* Ks   = (const float*)d_in[6];
    float* out = (float*)d_out;

    const int smem_bytes = (2*STAGEF + BM*PSTR) * sizeof(float);  // 169,984 B
    cudaFuncSetAttribute(attn_kernel, cudaFuncAttributeMaxDynamicSharedMemorySize, smem_bytes);

    mats_kernel<<<1, 32>>>(vm, Ks);
    preproc_kernel<<<(SQ*NHH*32 + 255)/256, 256>>>((const float4*)q, (const float4*)k,
                                                   (const float4*)v, cosb, sinb);
    attn_kernel<<<dim3((SQ + BM - 1)/BM, NHH, 2), 256, smem_bytes>>>(v, out);
    proj_out_kernel<<<(NEL/4 + 255)/256, 256>>>(out + NEL);
}

// round 5
// speedup vs baseline: 3.8506x; 1.0053x over previous
#include <cuda_runtime.h>
#include <math.h>

#define SQ   2640
#define TF   880
#define NHH  12
#define HDD  128
#define NEL  (SQ*NHH*HDD)
#define SCALE 0.088388347648318447f

#define BM 128
#define BN 64
#define KSTR 132
#define PSTR 68
#define STAGEF (2*BN*KSTR)          // floats per stage (K tile + V tile)
#define TILEF  (BN*KSTR)            // floats per K (or V) tile

__device__ float g_qr[NHH*SQ*HDD];
__device__ float g_kr[NHH*SQ*HDD];
__device__ float g_qp[NHH*SQ*HDD];
__device__ float g_kp[NHH*SQ*HDD];
__device__ float g_vp[NHH*SQ*HDD];
__device__ float g_po[SQ*NHH*HDD];
__device__ float g_P [3][16];
__device__ float g_Pi[3][16];

__device__ __forceinline__ float to_tf32(float x) {
    unsigned u;
    asm("cvt.rna.tf32.f32 %0, %1;" : "=r"(u) : "f"(x));
    return __uint_as_float(u);
}

__device__ __forceinline__ void cp_async16(unsigned dst, const void* src) {
    asm volatile("cp.async.cg.shared.global [%0], [%1], 16;" :: "r"(dst), "l"(src));
}

#define MMA_TF32(D, A, b0, b1)                                              \
  asm volatile("mma.sync.aligned.m16n8k8.row.col.f32.tf32.tf32.f32 "        \
    "{%0,%1,%2,%3},{%4,%5,%6,%7},{%8,%9},{%0,%1,%2,%3};"                    \
    : "+f"((D)[0]), "+f"((D)[1]), "+f"((D)[2]), "+f"((D)[3])                \
    : "r"(__float_as_uint((A)[0])), "r"(__float_as_uint((A)[1])),           \
      "r"(__float_as_uint((A)[2])), "r"(__float_as_uint((A)[3])),           \
      "r"(__float_as_uint(b0)), "r"(__float_as_uint(b1)))

__global__ void mats_kernel(const float* __restrict__ vm, const float* __restrict__ Ks) {
    int f = threadIdx.x;
    if (f >= 3) return;
    float P[16];
    for (int i = 0; i < 3; i++)
        for (int j = 0; j < 4; j++) {
            float s = 0.f;
            for (int k2 = 0; k2 < 3; k2++)
                s += Ks[f*9 + i*3 + k2] * vm[f*16 + k2*4 + j];
            P[i*4 + j] = s;
        }
    for (int j = 0; j < 4; j++) P[12 + j] = vm[f*16 + 12 + j];
    for (int i = 0; i < 16; i++) g_P[f][i] = P[i];

    double M[4][8];
    for (int i = 0; i < 4; i++)
        for (int j = 0; j < 4; j++) {
            M[i][j]     = (double)P[i*4 + j];
            M[i][4 + j] = (i == j) ? 1.0 : 0.0;
        }
    for (int col = 0; col < 4; col++) {
        int piv = col; double best = fabs(M[col][col]);
        for (int r = col + 1; r < 4; r++)
            if (fabs(M[r][col]) > best) { best = fabs(M[r][col]); piv = r; }
        if (piv != col)
            for (int j = 0; j < 8; j++) { double t = M[col][j]; M[col][j] = M[piv][j]; M[piv][j] = t; }
        double inv = 1.0 / M[col][col];
        for (int j = 0; j < 8; j++) M[col][j] *= inv;
        for (int r = 0; r < 4; r++) {
            if (r == col) continue;
            double fm = M[r][col];
            for (int j = 0; j < 8; j++) M[r][j] -= fm * M[col][j];
        }
    }
    for (int i = 0; i < 4; i++)
        for (int j = 0; j < 4; j++)
            g_Pi[f][i*4 + j] = (float)M[i][4 + j];
}

__global__ void preproc_kernel(const float4* __restrict__ q, const float4* __restrict__ k,
                               const float4* __restrict__ v, const float* __restrict__ cosb,
                               const float* __restrict__ sinb) {
    int t = blockIdx.x*blockDim.x + threadIdx.x;
    if (t >= SQ*NHH*32) return;
    int d4 = t & 31;
    int h  = (t >> 5) % NHH;
    int s  = t / (NHH*32);
    int f  = s / TF;

    float4 q4 = q[(s*NHH + h)*32 + d4];
    float4 k4 = k[(s*NHH + h)*32 + d4];
    float4 v4 = v[(s*NHH + h)*32 + d4];
    float c0 = cosb[s*64 + 2*d4], c1 = cosb[s*64 + 2*d4 + 1];
    float s0 = sinb[s*64 + 2*d4], s1 = sinb[s*64 + 2*d4 + 1];

    float4 qr, kr;
    qr.x = (q4.x*c0 - q4.y*s0)*SCALE; qr.y = (q4.y*c0 + q4.x*s0)*SCALE;
    qr.z = (q4.z*c1 - q4.w*s1)*SCALE; qr.w = (q4.w*c1 + q4.z*s1)*SCALE;
    kr.x = k4.x*c0 - k4.y*s0;         kr.y = k4.y*c0 + k4.x*s0;
    kr.z = k4.z*c1 - k4.w*s1;         kr.w = k4.w*c1 + k4.z*s1;

    const float* P  = g_P[f];
    const float* Pi = g_Pi[f];
    float4 qp, kp, vp;
    qp.x = (P[0] *q4.x + P[1] *q4.y + P[2] *q4.z + P[3] *q4.w)*SCALE;
    qp.y = (P[4] *q4.x + P[5] *q4.y + P[6] *q4.z + P[7] *q4.w)*SCALE;
    qp.z = (P[8] *q4.x + P[9] *q4.y + P[10]*q4.z + P[11]*q4.w)*SCALE;
    qp.w = (P[12]*q4.x + P[13]*q4.y + P[14]*q4.z + P[15]*q4.w)*SCALE;
    kp.x = Pi[0]*k4.x + Pi[4]*k4.y + Pi[8] *k4.z + Pi[12]*k4.w;
    kp.y = Pi[1]*k4.x + Pi[5]*k4.y + Pi[9] *k4.z + Pi[13]*k4.w;
    kp.z = Pi[2]*k4.x + Pi[6]*k4.y + Pi[10]*k4.z + Pi[14]*k4.w;
    kp.w = Pi[3]*k4.x + Pi[7]*k4.y + Pi[11]*k4.z + Pi[15]*k4.w;
    vp.x = Pi[0] *v4.x + Pi[1] *v4.y + Pi[2] *v4.z + Pi[3] *v4.w;
    vp.y = Pi[4] *v4.x + Pi[5] *v4.y + Pi[6] *v4.z + Pi[7] *v4.w;
    vp.z = Pi[8] *v4.x + Pi[9] *v4.y + Pi[10]*v4.z + Pi[11]*v4.w;
    vp.w = Pi[12]*v4.x + Pi[13]*v4.y + Pi[14]*v4.z + Pi[15]*v4.w;

    qr.x = to_tf32(qr.x); qr.y = to_tf32(qr.y); qr.z = to_tf32(qr.z); qr.w = to_tf32(qr.w);
    kr.x = to_tf32(kr.x); kr.y = to_tf32(kr.y); kr.z = to_tf32(kr.z); kr.w = to_tf32(kr.w);
    qp.x = to_tf32(qp.x); qp.y = to_tf32(qp.y); qp.z = to_tf32(qp.z); qp.w = to_tf32(qp.w);
    kp.x = to_tf32(kp.x); kp.y = to_tf32(kp.y); kp.z = to_tf32(kp.z); kp.w = to_tf32(kp.w);
    vp.x = to_tf32(vp.x); vp.y = to_tf32(vp.y); vp.z = to_tf32(vp.z); vp.w = to_tf32(vp.w);

    int o = (h*SQ + s)*32 + d4;
    ((float4*)g_qr)[o] = qr;
    ((float4*)g_kr)[o] = kr;
    ((float4*)g_qp)[o] = qp;
    ((float4*)g_kp)[o] = kp;
    ((float4*)g_vp)[o] = vp;
}

__global__ __launch_bounds__(256, 1) void attn_kernel(const float* __restrict__ vin,
                                                      float* __restrict__ out0) {
    extern __shared__ float sm[];
    // [stage0: K(8448) V(8448)][stage1: K V][sP: 128*68]
    float* sPb = sm + 2*STAGEF;

    int kind = blockIdx.z, h = blockIdx.y;
    int row0 = (gridDim.x - 1 - blockIdx.x) * BM;   // longest blocks first
    int tid = threadIdx.x;
    int w = tid >> 5, lane = tid & 31, g = lane >> 2, a = lane & 3;

    unsigned smem_u32 = (unsigned)__cvta_generic_to_shared(sm);
    float* sP = sPb + w*16*PSTR;

    const float* Q = (kind ? g_qp : g_qr) + h*SQ*HDD;
    const float* K = (kind ? g_kp : g_kr) + h*SQ*HDD;
    const float* Vb; int vstr;
    if (kind) { Vb = g_vp + h*SQ*HDD; vstr = HDD; }
    else      { Vb = vin  + h*HDD;    vstr = NHH*HDD; }
    float* Out = kind ? g_po : out0;

    int rw  = row0 + w*16;
    int ra  = rw + g, rb = rw + g + 8;
    int rca = min(ra, SQ-1), rcb = min(rb, SQ-1);
    int kma = (rca/TF + 1)*TF;
    int kmb = (rcb/TF + 1)*TF;

    float qf[16][4];
    {
        const float* Qa = Q + rca*HDD;
        const float* Qb = Q + rcb*HDD;
        #pragma unroll
        for (int ks = 0; ks < 16; ks++) {
            qf[ks][0] = Qa[8*ks + a];
            qf[ks][1] = Qb[8*ks + a];
            qf[ks][2] = Qa[8*ks + a + 4];
            qf[ks][3] = Qb[8*ks + a + 4];
        }
    }

    float of[16][4];
    #pragma unroll
    for (int n = 0; n < 16; n++) { of[n][0]=0.f; of[n][1]=0.f; of[n][2]=0.f; of[n][3]=0.f; }
    float m0 = -1e30f, m1 = -1e30f, l0 = 0.f, l1 = 0.f;

    int kend = (min(row0 + BM - 1, SQ-1)/TF + 1)*TF;

    // ---- cp.async tile loader ----
    auto issue_tile = [&](int j0, int st) {
        unsigned kbase = smem_u32 + (unsigned)(st*STAGEF)*4u;
        unsigned vbase = kbase + (unsigned)TILEF*4u;
        #pragma unroll
        for (int it = 0; it < 8; it++) {
            int idx = tid + it*256;
            int col = idx >> 5;
            int c4  = (idx & 31) << 2;
            int gc  = min(j0 + col, SQ-1);
            cp_async16(kbase + (unsigned)(col*KSTR + c4)*4u, K  + gc*HDD  + c4);
            cp_async16(vbase + (unsigned)(col*KSTR + c4)*4u, Vb + gc*vstr + c4);
        }
    };

    issue_tile(0, 0);
    asm volatile("cp.async.commit_group;");
    issue_tile(BN, 1);
    asm volatile("cp.async.commit_group;");

    int st = 0;
    for (int j0 = 0; j0 < kend; j0 += BN, st ^= 1) {
        asm volatile("cp.async.wait_group 1;");
        __syncthreads();

        const float* sK = sm + st*STAGEF;
        const float* sV = sK + TILEF;

        float sf[8][4];
        #pragma unroll
        for (int n = 0; n < 8; n++) { sf[n][0]=0.f; sf[n][1]=0.f; sf[n][2]=0.f; sf[n][3]=0.f; }

        #pragma unroll
        for (int ks = 0; ks < 16; ks++) {
            #pragma unroll
            for (int n = 0; n < 8; n++) {
                float b0 = sK[(n*8 + g)*KSTR + 8*ks + a];
                float b1 = sK[(n*8 + g)*KSTR + 8*ks + a + 4];
                MMA_TF32(sf[n], qf[ks], b0, b1);
            }
        }

        #pragma unroll
        for (int n = 0; n < 8; n++) {
            int c0 = j0 + n*8 + 2*a;
            if (c0     >= kma) sf[n][0] = -1e30f;
            if (c0 + 1 >= kma) sf[n][1] = -1e30f;
            if (c0     >= kmb) sf[n][2] = -1e30f;
            if (c0 + 1 >= kmb) sf[n][3] = -1e30f;
        }

        float mx0 = -1e30f, mx1 = -1e30f;
        #pragma unroll
        for (int n = 0; n < 8; n++) {
            mx0 = fmaxf(mx0, fmaxf(sf[n][0], sf[n][1]));
            mx1 = fmaxf(mx1, fmaxf(sf[n][2], sf[n][3]));
        }
        mx0 = fmaxf(mx0, __shfl_xor_sync(0xffffffffu, mx0, 1));
        mx0 = fmaxf(mx0, __shfl_xor_sync(0xffffffffu, mx0, 2));
        mx1 = fmaxf(mx1, __shfl_xor_sync(0xffffffffu, mx1, 1));
        mx1 = fmaxf(mx1, __shfl_xor_sync(0xffffffffu, mx1, 2));

        float mn0 = fmaxf(m0, mx0), mn1 = fmaxf(m1, mx1);
        float al0 = __expf(m0 - mn0), al1 = __expf(m1 - mn1);
        float ps0 = 0.f, ps1 = 0.f;
        #pragma unroll
        for (int n = 0; n < 8; n++) {
            float p00 = to_tf32(__expf(sf[n][0] - mn0));
            float p01 = to_tf32(__expf(sf[n][1] - mn0));
            float p10 = to_tf32(__expf(sf[n][2] - mn1));
            float p11 = to_tf32(__expf(sf[n][3] - mn1));
            ps0 += p00 + p01;
            ps1 += p10 + p11;
            *(float2*)(sP + g*PSTR     + n*8 + 2*a) = make_float2(p00, p01);
            *(float2*)(sP + (g+8)*PSTR + n*8 + 2*a) = make_float2(p10, p11);
        }
        ps0 += __shfl_xor_sync(0xffffffffu, ps0, 1);
        ps0 += __shfl_xor_sync(0xffffffffu, ps0, 2);
        ps1 += __shfl_xor_sync(0xffffffffu, ps1, 1);
        ps1 += __shfl_xor_sync(0xffffffffu, ps1, 2);
        l0 = l0*al0 + ps0;  l1 = l1*al1 + ps1;
        m0 = mn0;           m1 = mn1;

        #pragma unroll
        for (int n = 0; n < 16; n++) {
            of[n][0] *= al0; of[n][1] *= al0;
            of[n][2] *= al1; of[n][3] *= al1;
        }

        #pragma unroll
        for (int ks = 0; ks < 8; ks++) {
            float pa[4];
            pa[0] = sP[g*PSTR     + 8*ks + a];
            pa[1] = sP[(g+8)*PSTR + 8*ks + a];
            pa[2] = sP[g*PSTR     + 8*ks + a + 4];
            pa[3] = sP[(g+8)*PSTR + 8*ks + a + 4];
            #pragma unroll
            for (int n = 0; n < 16; n++) {
                float b0 = sV[(8*ks + a)*KSTR     + n*8 + g];
                float b1 = sV[(8*ks + a + 4)*KSTR + n*8 + g];
                MMA_TF32(of[n], pa, b0, b1);
            }
        }

        __syncthreads();              // everyone done with stage st
        int jn = j0 + 2*BN;
        if (jn < kend) issue_tile(jn, st);
        asm volatile("cp.async.commit_group;");   // commit (possibly empty) to keep counts aligned
    }

    float li0 = 1.f / l0, li1 = 1.f / l1;
    if (ra < SQ) {
        float* da = Out + ra*(NHH*HDD) + h*HDD;
        #pragma unroll
        for (int n = 0; n < 16; n++)
            *(float2*)(da + n*8 + 2*a) = make_float2(of[n][0]*li0, of[n][1]*li0);
    }
    if (rb < SQ) {
        float* db = Out + rb*(NHH*HDD) + h*HDD;
        #pragma unroll
        for (int n = 0; n < 16; n++)
            *(float2*)(db + n*8 + 2*a) = make_float2(of[n][2]*li1, of[n][3]*li1);
    }
}

__global__ void proj_out_kernel(float* __restrict__ out1) {
    int idx4 = blockIdx.x*blockDim.x + threadIdx.x;
    if (idx4 >= NEL/4) return;
    int idx = idx4 << 2;
    int s = idx / (NHH*HDD);
    int f = s / TF;
    const float* P = g_P[f];
    float4 po = *(const float4*)(g_po + idx);
    float4 o;
    o.x = P[0] *po.x + P[1] *po.y + P[2] *po.z + P[3] *po.w;
    o.y = P[4] *po.x + P[5] *po.y + P[6] *po.z + P[7] *po.w;
    o.z = P[8] *po.x + P[9] *po.y + P[10]*po.z + P[11]*po.w;
    o.w = P[12]*po.x + P[13]*po.y + P[14]*po.z + P[15]*po.w;
    *(float4*)(out1 + idx) = o;
}

extern "C" void kernel_launch(void* const* d_in, const int* in_sizes, int n_in,
                              void* d_out, int out_size) {
    const float* q    = (const float*)d_in[0];
    const float* k    = (const float*)d_in[1];
    const float* v    = (const float*)d_in[2];
    const float* cosb = (const float*)d_in[3];
    const float* sinb = (const float*)d_in[4];
    const float* vm   = (const float*)d_in[5];
    const float* Ks   = (const float*)d_in[6];
    float* out = (float*)d_out;

    const int smem_bytes = (2*STAGEF + BM*PSTR) * sizeof(float);  // 169,984 B
    cudaFuncSetAttribute(attn_kernel, cudaFuncAttributeMaxDynamicSharedMemorySize, smem_bytes);

    mats_kernel<<<1, 32>>>(vm, Ks);
    preproc_kernel<<<(SQ*NHH*32 + 255)/256, 256>>>((const float4*)q, (const float4*)k,
                                                   (const float4*)v, cosb, sinb);
    attn_kernel<<<dim3((SQ + BM - 1)/BM, NHH, 2), 256, smem_bytes>>>(v, out);
    proj_out_kernel<<<(NEL/4 + 255)/256, 256>>>(out + NEL);
}

// round 7
// speedup vs baseline: 9.7307x; 2.5271x over previous
#include <cuda_runtime.h>
#include <cuda_fp16.h>
#include <math.h>
#include <stdint.h>

#define SQ   2640
#define TF   880
#define NHH  12
#define HDD  128
#define NEL  (SQ*NHH*HDD)
#define SCALE 0.088388347648318447f

#define BM 128
#define BN 64
#define KTILE_B 16384          // 64 rows x 256 B (fp16)
#define VTILE_B 16384          // 128 rows x 128 B
#define STAGE_B (KTILE_B + VTILE_B)

// ---------------- device scratch ----------------
__device__ __half g_qrh[NHH*SQ*HDD];        // rope Q [h][s][d]
__device__ __half g_krh[NHH*SQ*HDD];        // rope K
__device__ __half g_qph[NHH*SQ*HDD];        // prope Q
__device__ __half g_kph[NHH*SQ*HDD];        // prope K
__device__ __half g_vrh[NHH*HDD*SQ + 64];   // V^T [h][d][s] (+pad for tile overshoot)
__device__ __half g_vph[NHH*HDD*SQ + 64];   // (Pinv V)^T
__device__ float  g_po [SQ*NHH*HDD];        // prope attn out (pre-projection)
__device__ float  g_P  [3][16];
__device__ float  g_Pi [3][16];

// ---------------- helpers ----------------
__device__ __forceinline__ uint32_t smem_u32(const void* p) {
    return (uint32_t)__cvta_generic_to_shared(p);
}
__device__ __forceinline__ void cp_async16(uint32_t dst, const void* src) {
    asm volatile("cp.async.cg.shared.global [%0], [%1], 16;" :: "r"(dst), "l"(src));
}
#define CP_COMMIT() asm volatile("cp.async.commit_group;")

#define LDSM_X4(r0,r1,r2,r3,addr) \
    asm volatile("ldmatrix.sync.aligned.m8n8.x4.shared.b16 {%0,%1,%2,%3}, [%4];" \
        : "=r"(r0), "=r"(r1), "=r"(r2), "=r"(r3) : "r"(addr))

#define MMA_F16(D, A, b0, b1)                                                \
  asm volatile("mma.sync.aligned.m16n8k16.row.col.f32.f16.f16.f32 "          \
    "{%0,%1,%2,%3},{%4,%5,%6,%7},{%8,%9},{%0,%1,%2,%3};"                     \
    : "+f"((D)[0]), "+f"((D)[1]), "+f"((D)[2]), "+f"((D)[3])                 \
    : "r"((A)[0]), "r"((A)[1]), "r"((A)[2]), "r"((A)[3]), "r"(b0), "r"(b1))

__device__ __forceinline__ uint32_t pack_h2(float lo, float hi) {
    __half2 h = __floats2half2_rn(lo, hi);   // .x = lo (lower k), .y = hi
    return *(uint32_t*)&h;
}

// ---------------- kernel 1: P, Pinv ----------------
__global__ void mats_kernel(const float* __restrict__ vm, const float* __restrict__ Ks) {
    int f = threadIdx.x;
    if (f >= 3) return;
    float P[16];
    for (int i = 0; i < 3; i++)
        for (int j = 0; j < 4; j++) {
            float s = 0.f;
            for (int k2 = 0; k2 < 3; k2++)
                s += Ks[f*9 + i*3 + k2] * vm[f*16 + k2*4 + j];
            P[i*4 + j] = s;
        }
    for (int j = 0; j < 4; j++) P[12 + j] = vm[f*16 + 12 + j];
    for (int i = 0; i < 16; i++) g_P[f][i] = P[i];

    double M[4][8];
    for (int i = 0; i < 4; i++)
        for (int j = 0; j < 4; j++) {
            M[i][j] = (double)P[i*4 + j];
            M[i][4 + j] = (i == j) ? 1.0 : 0.0;
        }
    for (int col = 0; col < 4; col++) {
        int piv = col; double best = fabs(M[col][col]);
        for (int r = col + 1; r < 4; r++)
            if (fabs(M[r][col]) > best) { best = fabs(M[r][col]); piv = r; }
        if (piv != col)
            for (int j = 0; j < 8; j++) { double t = M[col][j]; M[col][j] = M[piv][j]; M[piv][j] = t; }
        double inv = 1.0 / M[col][col];
        for (int j = 0; j < 8; j++) M[col][j] *= inv;
        for (int r = 0; r < 4; r++) {
            if (r == col) continue;
            double fm = M[r][col];
            for (int j = 0; j < 8; j++) M[r][j] -= fm * M[col][j];
        }
    }
    for (int i = 0; i < 4; i++)
        for (int j = 0; j < 4; j++)
            g_Pi[f][i*4 + j] = (float)M[i][4 + j];
}

// ---------------- kernel 2: RoPE + projective Q,K -> fp16 ----------------
__global__ void preproc_kernel(const float4* __restrict__ q, const float4* __restrict__ k,
                               const float* __restrict__ cosb, const float* __restrict__ sinb) {
    int t = blockIdx.x*blockDim.x + threadIdx.x;
    if (t >= SQ*NHH*32) return;
    int d4 = t & 31;
    int h  = (t >> 5) % NHH;
    int s  = t / (NHH*32);
    int f  = s / TF;

    float4 q4 = q[(s*NHH + h)*32 + d4];
    float4 k4 = k[(s*NHH + h)*32 + d4];
    float c0 = cosb[s*64 + 2*d4], c1 = cosb[s*64 + 2*d4 + 1];
    float s0 = sinb[s*64 + 2*d4], s1 = sinb[s*64 + 2*d4 + 1];

    float4 qr, kr;
    qr.x = q4.x*c0 - q4.y*s0; qr.y = q4.y*c0 + q4.x*s0;
    qr.z = q4.z*c1 - q4.w*s1; qr.w = q4.w*c1 + q4.z*s1;
    kr.x = k4.x*c0 - k4.y*s0; kr.y = k4.y*c0 + k4.x*s0;
    kr.z = k4.z*c1 - k4.w*s1; kr.w = k4.w*c1 + k4.z*s1;

    const float* P  = g_P[f];
    const float* Pi = g_Pi[f];
    float4 qp, kp;
    qp.x = P[0] *q4.x + P[1] *q4.y + P[2] *q4.z + P[3] *q4.w;
    qp.y = P[4] *q4.x + P[5] *q4.y + P[6] *q4.z + P[7] *q4.w;
    qp.z = P[8] *q4.x + P[9] *q4.y + P[10]*q4.z + P[11]*q4.w;
    qp.w = P[12]*q4.x + P[13]*q4.y + P[14]*q4.z + P[15]*q4.w;
    kp.x = Pi[0]*k4.x + Pi[4]*k4.y + Pi[8] *k4.z + Pi[12]*k4.w;  // Pinv^T @ k
    kp.y = Pi[1]*k4.x + Pi[5]*k4.y + Pi[9] *k4.z + Pi[13]*k4.w;
    kp.z = Pi[2]*k4.x + Pi[6]*k4.y + Pi[10]*k4.z + Pi[14]*k4.w;
    kp.w = Pi[3]*k4.x + Pi[7]*k4.y + Pi[11]*k4.z + Pi[15]*k4.w;

    size_t o = ((size_t)h*SQ + s)*HDD + d4*4;
    *(__half2*)(g_qrh + o)     = __floats2half2_rn(qr.x, qr.y);
    *(__half2*)(g_qrh + o + 2) = __floats2half2_rn(qr.z, qr.w);
    *(__half2*)(g_krh + o)     = __floats2half2_rn(kr.x, kr.y);
    *(__half2*)(g_krh + o + 2) = __floats2half2_rn(kr.z, kr.w);
    *(__half2*)(g_qph + o)     = __floats2half2_rn(qp.x, qp.y);
    *(__half2*)(g_qph + o + 2) = __floats2half2_rn(qp.z, qp.w);
    *(__half2*)(g_kph + o)     = __floats2half2_rn(kp.x, kp.y);
    *(__half2*)(g_kph + o + 2) = __floats2half2_rn(kp.z, kp.w);
}

// ---------------- kernel 3: V transpose + Pinv@V -> fp16 [h][d][s] ----------------
__global__ void vtrans_kernel(const float* __restrict__ v) {
    __shared__ float smv[32][33];
    int h  = blockIdx.z;
    int d0 = blockIdx.y * 32;
    int s0 = blockIdx.x * 32;
    int tx = threadIdx.x, ty = threadIdx.y;

    for (int i = ty; i < 32; i += 8) {
        int s = s0 + i;
        smv[i][tx] = (s < SQ) ? v[((size_t)s*NHH + h)*HDD + d0 + tx] : 0.f;
    }
    __syncthreads();

    int sw = s0 + tx;
    if (sw < SQ) {
        const float* Pi = g_Pi[sw / TF];
        for (int i = ty; i < 32; i += 8) {
            int d = d0 + i;
            int gb = i & ~3, a = i & 3;
            float vp = Pi[a*4+0]*smv[tx][gb]   + Pi[a*4+1]*smv[tx][gb+1]
                     + Pi[a*4+2]*smv[tx][gb+2] + Pi[a*4+3]*smv[tx][gb+3];
            g_vrh[((size_t)h*HDD + d)*SQ + sw] = __float2half_rn(smv[tx][i]);
            g_vph[((size_t)h*HDD + d)*SQ + sw] = __float2half_rn(vp);
        }
    }
}

// ---------------- kernel 4: fp16 flash attention ----------------
__global__ __launch_bounds__(256, 1) void attn_kernel(float* __restrict__ out0) {
    extern __shared__ char smc[];
    uint32_t sb = smem_u32(smc);

    int kind = blockIdx.z, h = blockIdx.y;
    int row0 = (gridDim.x - 1 - blockIdx.x) * BM;   // longest blocks first
    int tid = threadIdx.x;
    int w = tid >> 5, lane = tid & 31, g = lane >> 2, a = lane & 3;
    int r8 = lane & 7, mhi = lane >> 3;
    int knp = ((mhi >> 1) << 3) + r8;   // row-within-matrix-pair: 0..15
    int mb  = mhi & 1;                  // k-chunk parity
    int ksw = knp & 7;                  // swizzle key

    const __half* Q  = (kind ? g_qph : g_qrh) + (size_t)h*SQ*HDD;
    const __half* K  = (kind ? g_kph : g_krh) + (size_t)h*SQ*HDD;
    const __half* Vt = (kind ? g_vph : g_vrh) + (size_t)h*HDD*SQ;
    float* Out = kind ? g_po : out0;

    int rw  = row0 + w*16;
    int ra  = rw + g, rb = rw + g + 8;
    int rca = min(ra, SQ-1), rcb = min(rb, SQ-1);
    int kma = (rca/TF + 1)*TF;
    int kmb = (rcb/TF + 1)*TF;
    int kend = (min(row0 + BM - 1, SQ-1)/TF + 1)*TF;
    int nt = (kend + BN - 1)/BN;

    // Q fragments (8 k16-steps x 4 regs), loaded once
    uint32_t qf[8][4];
    {
        const uint32_t* Qa = (const uint32_t*)(Q + (size_t)rca*HDD);
        const uint32_t* Qb = (const uint32_t*)(Q + (size_t)rcb*HDD);
        #pragma unroll
        for (int ks = 0; ks < 8; ks++) {
            qf[ks][0] = Qa[8*ks + a];
            qf[ks][1] = Qb[8*ks + a];
            qf[ks][2] = Qa[8*ks + a + 4];
            qf[ks][3] = Qb[8*ks + a + 4];
        }
    }

    float of[16][4];
    #pragma unroll
    for (int n = 0; n < 16; n++) { of[n][0]=0.f; of[n][1]=0.f; of[n][2]=0.f; of[n][3]=0.f; }
    float ps0 = 0.f, ps1 = 0.f;

    // ---- cp.async tile loader (swizzled 16B chunks) ----
    auto issue_tile = [&](int j0, int stg) {
        uint32_t kb = sb + (uint32_t)stg*STAGE_B;
        uint32_t vb = kb + KTILE_B;
        #pragma unroll
        for (int it = 0; it < 4; it++) {           // K: 64 rows x 16 chunks
            int idx = tid + it*256;
            int r = idx >> 4, c = idx & 15;
            cp_async16(kb + (uint32_t)(r*256 + ((c ^ (r & 7)) << 4)),
                       K + (size_t)min(j0 + r, SQ-1)*HDD + c*8);
        }
        #pragma unroll
        for (int it = 0; it < 4; it++) {           // V: 128 rows x 8 chunks
            int idx = tid + it*256;
            int d = idx >> 3, c = idx & 7;
            cp_async16(vb + (uint32_t)(d*128 + ((c ^ (d & 7)) << 4)),
                       Vt + (size_t)d*SQ + j0 + c*8);
        }
    };

    issue_tile(0, 0);
    CP_COMMIT();
    issue_tile(BN, 1);
    CP_COMMIT();

    int st = 0;
    for (int j = 0; j < nt; j++, st ^= 1) {
        asm volatile("cp.async.wait_group 1;");
        __syncthreads();

        uint32_t kbase = sb + (uint32_t)st*STAGE_B;
        uint32_t vbase = kbase + KTILE_B;

        // ---- QK: S = Q K^T (64 MMAs, B via ldmatrix) ----
        float sf[8][4];
        #pragma unroll
        for (int n = 0; n < 8; n++) { sf[n][0]=0.f; sf[n][1]=0.f; sf[n][2]=0.f; sf[n][3]=0.f; }

        #pragma unroll
        for (int ks = 0; ks < 8; ks++) {
            #pragma unroll
            for (int nb2 = 0; nb2 < 4; nb2++) {
                uint32_t b0, b1, b2, b3;
                uint32_t addr = kbase + (uint32_t)(nb2*4096 + knp*256
                              + ((((ks << 1) | mb) ^ ksw) << 4));
                LDSM_X4(b0, b1, b2, b3, addr);
                MMA_F16(sf[2*nb2],     qf[ks], b0, b1);
                MMA_F16(sf[2*nb2 + 1], qf[ks], b2, b3);
            }
        }

        // ---- softmax (no-max), pack P to fp16 A-frags in registers ----
        int j0 = j*BN;
        uint32_t pa[4][4];
        #pragma unroll
        for (int nb = 0; nb < 8; nb++) {
            int c0 = j0 + nb*8 + 2*a;
            float p0 = (c0     < kma) ? __expf(sf[nb][0]*SCALE) : 0.f;
            float p1 = (c0 + 1 < kma) ? __expf(sf[nb][1]*SCALE) : 0.f;
            float p2 = (c0     < kmb) ? __expf(sf[nb][2]*SCALE) : 0.f;
            float p3 = (c0 + 1 < kmb) ? __expf(sf[nb][3]*SCALE) : 0.f;
            ps0 += p0 + p1;
            ps1 += p2 + p3;
            int kt = nb >> 1;
            if ((nb & 1) == 0) { pa[kt][0] = pack_h2(p0, p1); pa[kt][1] = pack_h2(p2, p3); }
            else               { pa[kt][2] = pack_h2(p0, p1); pa[kt][3] = pack_h2(p2, p3); }
        }

        // ---- PV: O += P V (64 MMAs) ----
        #pragma unroll
        for (int kt = 0; kt < 4; kt++) {
            #pragma unroll
            for (int db2 = 0; db2 < 8; db2++) {
                uint32_t b0, b1, b2, b3;
                uint32_t addr = vbase + (uint32_t)(db2*2048 + knp*128
                              + ((((kt << 1) | mb) ^ ksw) << 4));
                LDSM_X4(b0, b1, b2, b3, addr);
                MMA_F16(of[2*db2],     pa[kt], b0, b1);
                MMA_F16(of[2*db2 + 1], pa[kt], b2, b3);
            }
        }

        __syncthreads();
        int jn = j + 2;
        if (jn < nt) issue_tile(jn*BN, st);
        CP_COMMIT();
    }

    // ---- epilogue: one reduction, normalize, write ----
    ps0 += __shfl_xor_sync(0xffffffffu, ps0, 1);
    ps0 += __shfl_xor_sync(0xffffffffu, ps0, 2);
    ps1 += __shfl_xor_sync(0xffffffffu, ps1, 1);
    ps1 += __shfl_xor_sync(0xffffffffu, ps1, 2);
    float li0 = 1.f / ps0, li1 = 1.f / ps1;

    if (ra < SQ) {
        float* da = Out + (size_t)ra*(NHH*HDD) + h*HDD;
        #pragma unroll
        for (int n = 0; n < 16; n++)
            *(float2*)(da + n*8 + 2*a) = make_float2(of[n][0]*li0, of[n][1]*li0);
    }
    if (rb < SQ) {
        float* db = Out + (size_t)rb*(NHH*HDD) + h*HDD;
        #pragma unroll
        for (int n = 0; n < 16; n++)
            *(float2*)(db + n*8 + 2*a) = make_float2(of[n][2]*li1, of[n][3]*li1);
    }
}

// ---------------- kernel 5: final projection of prope output ----------------
__global__ void proj_out_kernel(float* __restrict__ out1) {
    int idx4 = blockIdx.x*blockDim.x + threadIdx.x;
    if (idx4 >= NEL/4) return;
    int idx = idx4 << 2;
    int s = idx / (NHH*HDD);
    int f = s / TF;
    const float* P = g_P[f];
    float4 po = *(const float4*)(g_po + idx);
    float4 o;
    o.x = P[0] *po.x + P[1] *po.y + P[2] *po.z + P[3] *po.w;
    o.y = P[4] *po.x + P[5] *po.y + P[6] *po.z + P[7] *po.w;
    o.z = P[8] *po.x + P[9] *po.y + P[10]*po.z + P[11]*po.w;
    o.w = P[12]*po.x + P[13]*po.y + P[14]*po.z + P[15]*po.w;
    *(float4*)(out1 + idx) = o;
}

// ---------------- launch ----------------
extern "C" void kernel_launch(void* const* d_in, const int* in_sizes, int n_in,
                              void* d_out, int out_size) {
    const float* q    = (const float*)d_in[0];
    const float* k    = (const float*)d_in[1];
    const float* v    = (const float*)d_in[2];
    const float* cosb = (const float*)d_in[3];
    const float* sinb = (const float*)d_in[4];
    const float* vm   = (const float*)d_in[5];
    const float* Ks   = (const float*)d_in[6];
    float* out = (float*)d_out;

    const int smem_bytes = 2*STAGE_B;   // 65,536 B
    cudaFuncSetAttribute(attn_kernel, cudaFuncAttributeMaxDynamicSharedMemorySize, smem_bytes);

    mats_kernel<<<1, 32>>>(vm, Ks);
    preproc_kernel<<<(SQ*NHH*32 + 255)/256, 256>>>((const float4*)q, (const float4*)k, cosb, sinb);
    vtrans_kernel<<<dim3((SQ + 31)/32, HDD/32, NHH), dim3(32, 8)>>>(v);
    attn_kernel<<<dim3((SQ + BM - 1)/BM, NHH, 2), 256, smem_bytes>>>(out);
    proj_out_kernel<<<(NEL/4 + 255)/256, 256>>>(out + NEL);
}

// round 8
// speedup vs baseline: 10.6636x; 1.0959x over previous
#include <cuda_runtime.h>
#include <cuda_fp16.h>
#include <math.h>
#include <stdint.h>

#define SQ   2640
#define TF   880
#define NHH  12
#define HDD  128
#define NEL  (SQ*NHH*HDD)
#define SCALE 0.088388347648318447f
#define QSC   0.12751744729777468f   // SCALE * log2(e)

#define BM 64
#define BN 64
#define NTH 128
#define KTILE_B 16384          // 64 rows x 256 B (fp16)
#define VTILE_B 16384          // 128 d x 128 B
#define STAGE_B (KTILE_B + VTILE_B)

// ---------------- device scratch ----------------
__device__ __half g_qrh[NHH*SQ*HDD];        // rope Q [h][s][d]  (*QSC)
__device__ __half g_krh[NHH*SQ*HDD];        // rope K
__device__ __half g_qph[NHH*SQ*HDD];        // prope Q (*QSC)
__device__ __half g_kph[NHH*SQ*HDD];        // prope K
__device__ __half g_vrh[NHH*HDD*SQ + 64];   // V^T [h][d][s]
__device__ __half g_vph[NHH*HDD*SQ + 64];   // (Pinv V)^T
__device__ float  g_P  [3][16];
__device__ float  g_Pi [3][16];

// ---------------- helpers ----------------
__device__ __forceinline__ uint32_t smem_u32(const void* p) {
    return (uint32_t)__cvta_generic_to_shared(p);
}
__device__ __forceinline__ void cp_async16(uint32_t dst, const void* src) {
    asm volatile("cp.async.cg.shared.global [%0], [%1], 16;" :: "r"(dst), "l"(src));
}
#define CP_COMMIT() asm volatile("cp.async.commit_group;")

#define LDSM_X4(r0,r1,r2,r3,addr) \
    asm volatile("ldmatrix.sync.aligned.m8n8.x4.shared.b16 {%0,%1,%2,%3}, [%4];" \
        : "=r"(r0), "=r"(r1), "=r"(r2), "=r"(r3) : "r"(addr))

#define MMA_F16(D, A, b0, b1)                                                \
  asm volatile("mma.sync.aligned.m16n8k16.row.col.f32.f16.f16.f32 "          \
    "{%0,%1,%2,%3},{%4,%5,%6,%7},{%8,%9},{%0,%1,%2,%3};"                     \
    : "+f"((D)[0]), "+f"((D)[1]), "+f"((D)[2]), "+f"((D)[3])                 \
    : "r"((A)[0]), "r"((A)[1]), "r"((A)[2]), "r"((A)[3]), "r"(b0), "r"(b1))

__device__ __forceinline__ uint32_t pack_h2(float lo, float hi) {
    __half2 h = __floats2half2_rn(lo, hi);
    return *(uint32_t*)&h;
}

// ---------------- kernel 1: P, Pinv ----------------
__global__ void mats_kernel(const float* __restrict__ vm, const float* __restrict__ Ks) {
    int f = threadIdx.x;
    if (f >= 3) return;
    float P[16];
    for (int i = 0; i < 3; i++)
        for (int j = 0; j < 4; j++) {
            float s = 0.f;
            for (int k2 = 0; k2 < 3; k2++)
                s += Ks[f*9 + i*3 + k2] * vm[f*16 + k2*4 + j];
            P[i*4 + j] = s;
        }
    for (int j = 0; j < 4; j++) P[12 + j] = vm[f*16 + 12 + j];
    for (int i = 0; i < 16; i++) g_P[f][i] = P[i];

    double M[4][8];
    for (int i = 0; i < 4; i++)
        for (int j = 0; j < 4; j++) {
            M[i][j] = (double)P[i*4 + j];
            M[i][4 + j] = (i == j) ? 1.0 : 0.0;
        }
    for (int col = 0; col < 4; col++) {
        int piv = col; double best = fabs(M[col][col]);
        for (int r = col + 1; r < 4; r++)
            if (fabs(M[r][col]) > best) { best = fabs(M[r][col]); piv = r; }
        if (piv != col)
            for (int j = 0; j < 8; j++) { double t = M[col][j]; M[col][j] = M[piv][j]; M[piv][j] = t; }
        double inv = 1.0 / M[col][col];
        for (int j = 0; j < 8; j++) M[col][j] *= inv;
        for (int r = 0; r < 4; r++) {
            if (r == col) continue;
            double fm = M[r][col];
            for (int j = 0; j < 8; j++) M[r][j] -= fm * M[col][j];
        }
    }
    for (int i = 0; i < 4; i++)
        for (int j = 0; j < 4; j++)
            g_Pi[f][i*4 + j] = (float)M[i][4 + j];
}

// ---------------- kernel 2: RoPE + projective Q,K -> fp16 ----------------
__global__ void preproc_kernel(const float4* __restrict__ q, const float4* __restrict__ k,
                               const float* __restrict__ cosb, const float* __restrict__ sinb) {
    int t = blockIdx.x*blockDim.x + threadIdx.x;
    if (t >= SQ*NHH*32) return;
    int d4 = t & 31;
    int h  = (t >> 5) % NHH;
    int s  = t / (NHH*32);
    int f  = s / TF;

    float4 q4 = q[(s*NHH + h)*32 + d4];
    float4 k4 = k[(s*NHH + h)*32 + d4];
    float c0 = cosb[s*64 + 2*d4], c1 = cosb[s*64 + 2*d4 + 1];
    float s0 = sinb[s*64 + 2*d4], s1 = sinb[s*64 + 2*d4 + 1];

    float4 qr, kr;
    qr.x = (q4.x*c0 - q4.y*s0)*QSC; qr.y = (q4.y*c0 + q4.x*s0)*QSC;
    qr.z = (q4.z*c1 - q4.w*s1)*QSC; qr.w = (q4.w*c1 + q4.z*s1)*QSC;
    kr.x = k4.x*c0 - k4.y*s0;       kr.y = k4.y*c0 + k4.x*s0;
    kr.z = k4.z*c1 - k4.w*s1;       kr.w = k4.w*c1 + k4.z*s1;

    const float* P  = g_P[f];
    const float* Pi = g_Pi[f];
    float4 qp, kp;
    qp.x = (P[0] *q4.x + P[1] *q4.y + P[2] *q4.z + P[3] *q4.w)*QSC;
    qp.y = (P[4] *q4.x + P[5] *q4.y + P[6] *q4.z + P[7] *q4.w)*QSC;
    qp.z = (P[8] *q4.x + P[9] *q4.y + P[10]*q4.z + P[11]*q4.w)*QSC;
    qp.w = (P[12]*q4.x + P[13]*q4.y + P[14]*q4.z + P[15]*q4.w)*QSC;
    kp.x = Pi[0]*k4.x + Pi[4]*k4.y + Pi[8] *k4.z + Pi[12]*k4.w;  // Pinv^T @ k
    kp.y = Pi[1]*k4.x + Pi[5]*k4.y + Pi[9] *k4.z + Pi[13]*k4.w;
    kp.z = Pi[2]*k4.x + Pi[6]*k4.y + Pi[10]*k4.z + Pi[14]*k4.w;
    kp.w = Pi[3]*k4.x + Pi[7]*k4.y + Pi[11]*k4.z + Pi[15]*k4.w;

    size_t o = ((size_t)h*SQ + s)*HDD + d4*4;
    *(__half2*)(g_qrh + o)     = __floats2half2_rn(qr.x, qr.y);
    *(__half2*)(g_qrh + o + 2) = __floats2half2_rn(qr.z, qr.w);
    *(__half2*)(g_krh + o)     = __floats2half2_rn(kr.x, kr.y);
    *(__half2*)(g_krh + o + 2) = __floats2half2_rn(kr.z, kr.w);
    *(__half2*)(g_qph + o)     = __floats2half2_rn(qp.x, qp.y);
    *(__half2*)(g_qph + o + 2) = __floats2half2_rn(qp.z, qp.w);
    *(__half2*)(g_kph + o)     = __floats2half2_rn(kp.x, kp.y);
    *(__half2*)(g_kph + o + 2) = __floats2half2_rn(kp.z, kp.w);
}

// ---------------- kernel 3: V transpose + Pinv@V -> fp16 [h][d][s] ----------------
__global__ void vtrans_kernel(const float* __restrict__ v) {
    __shared__ float smv[32][33];
    int h  = blockIdx.z;
    int d0 = blockIdx.y * 32;
    int s0 = blockIdx.x * 32;
    int tx = threadIdx.x, ty = threadIdx.y;

    for (int i = ty; i < 32; i += 8) {
        int s = s0 + i;
        smv[i][tx] = (s < SQ) ? v[((size_t)s*NHH + h)*HDD + d0 + tx] : 0.f;
    }
    __syncthreads();

    int sw = s0 + tx;
    if (sw < SQ) {
        const float* Pi = g_Pi[sw / TF];
        for (int i = ty; i < 32; i += 8) {
            int d = d0 + i;
            int gb = i & ~3, a = i & 3;
            float vp = Pi[a*4+0]*smv[tx][gb]   + Pi[a*4+1]*smv[tx][gb+1]
                     + Pi[a*4+2]*smv[tx][gb+2] + Pi[a*4+3]*smv[tx][gb+3];
            g_vrh[((size_t)h*HDD + d)*SQ + sw] = __float2half_rn(smv[tx][i]);
            g_vph[((size_t)h*HDD + d)*SQ + sw] = __float2half_rn(vp);
        }
    }
}

// ---------------- kernel 4: fp16 flash attention ----------------
__global__ __launch_bounds__(NTH, 2) void attn_kernel(float* __restrict__ out) {
    extern __shared__ char smc[];
    uint32_t sb = smem_u32(smc);

    int kind = blockIdx.z, h = blockIdx.y;
    int row0 = (gridDim.x - 1 - blockIdx.x) * BM;   // longest blocks first
    int tid = threadIdx.x;
    int w = tid >> 5, lane = tid & 31, g = lane >> 2, a = lane & 3;
    int r8 = lane & 7, mhi = lane >> 3;
    int knp = ((mhi >> 1) << 3) + r8;   // row within matrix pair: 0..15
    int mb  = mhi & 1;                  // k-chunk parity
    int ksw = knp & 7;                  // swizzle key

    const __half* Q  = (kind ? g_qph : g_qrh) + (size_t)h*SQ*HDD;
    const __half* K  = (kind ? g_kph : g_krh) + (size_t)h*SQ*HDD;
    const __half* Vt = (kind ? g_vph : g_vrh) + (size_t)h*HDD*SQ;
    float* Out = out + (size_t)kind*NEL;

    int rw  = row0 + w*16;
    int ra  = rw + g, rb = rw + g + 8;
    int rca = min(ra, SQ-1), rcb = min(rb, SQ-1);
    int kma = (rca/TF + 1)*TF;
    int kmb = (rcb/TF + 1)*TF;
    int kmw = (min(rw, SQ-1)/TF + 1)*TF;   // warp-min mask bound
    int kend = (min(row0 + BM - 1, SQ-1)/TF + 1)*TF;
    int nt = (kend + BN - 1)/BN;

    // Q fragments (8 k16-steps x 4 regs)
    uint32_t qf[8][4];
    {
        const uint32_t* Qa = (const uint32_t*)(Q + (size_t)rca*HDD);
        const uint32_t* Qb = (const uint32_t*)(Q + (size_t)rcb*HDD);
        #pragma unroll
        for (int ks = 0; ks < 8; ks++) {
            qf[ks][0] = Qa[8*ks + a];
            qf[ks][1] = Qb[8*ks + a];
            qf[ks][2] = Qa[8*ks + a + 4];
            qf[ks][3] = Qb[8*ks + a + 4];
        }
    }

    float of[16][4];
    #pragma unroll
    for (int n = 0; n < 16; n++) { of[n][0]=0.f; of[n][1]=0.f; of[n][2]=0.f; of[n][3]=0.f; }
    float ps0 = 0.f, ps1 = 0.f;

    auto issue_tile = [&](int j0, int stg) {
        uint32_t kb = sb + (uint32_t)stg*STAGE_B;
        uint32_t vb = kb + KTILE_B;
        #pragma unroll
        for (int it = 0; it < 8; it++) {           // K: 64 rows x 16 chunks
            int idx = tid + it*NTH;
            int r = idx >> 4, c = idx & 15;
            cp_async16(kb + (uint32_t)(r*256 + ((c ^ (r & 7)) << 4)),
                       K + (size_t)min(j0 + r, SQ-1)*HDD + c*8);
        }
        #pragma unroll
        for (int it = 0; it < 8; it++) {           // V: 128 d x 8 chunks
            int idx = tid + it*NTH;
            int d = idx >> 3, c = idx & 7;
            cp_async16(vb + (uint32_t)(d*128 + ((c ^ (d & 7)) << 4)),
                       Vt + (size_t)d*SQ + j0 + c*8);
        }
    };

    issue_tile(0, 0);
    CP_COMMIT();
    issue_tile(BN, 1);
    CP_COMMIT();

    int st = 0;
    for (int j = 0; j < nt; j++, st ^= 1) {
        asm volatile("cp.async.wait_group 1;");
        __syncthreads();

        uint32_t kbase = sb + (uint32_t)st*STAGE_B;
        uint32_t vbase = kbase + KTILE_B;

        // ---- QK ----
        float sf[8][4];
        #pragma unroll
        for (int n = 0; n < 8; n++) { sf[n][0]=0.f; sf[n][1]=0.f; sf[n][2]=0.f; sf[n][3]=0.f; }

        #pragma unroll
        for (int ks = 0; ks < 8; ks++) {
            #pragma unroll
            for (int nb2 = 0; nb2 < 4; nb2++) {
                uint32_t b0, b1, b2, b3;
                uint32_t addr = kbase + (uint32_t)(nb2*4096 + knp*256
                              + ((((ks << 1) | mb) ^ ksw) << 4));
                LDSM_X4(b0, b1, b2, b3, addr);
                MMA_F16(sf[2*nb2],     qf[ks], b0, b1);
                MMA_F16(sf[2*nb2 + 1], qf[ks], b2, b3);
            }
        }

        // ---- softmax (no-max, exp2), pack P fragments ----
        int j0 = j*BN;
        uint32_t pa[4][4];
        if (j0 + BN <= kmw) {                 // interior tile: no masking
            #pragma unroll
            for (int nb = 0; nb < 8; nb++) {
                float p0 = exp2f(sf[nb][0]);
                float p1 = exp2f(sf[nb][1]);
                float p2 = exp2f(sf[nb][2]);
                float p3 = exp2f(sf[nb][3]);
                ps0 += p0 + p1;
                ps1 += p2 + p3;
                int kt = nb >> 1;
                if ((nb & 1) == 0) { pa[kt][0] = pack_h2(p0, p1); pa[kt][1] = pack_h2(p2, p3); }
                else               { pa[kt][2] = pack_h2(p0, p1); pa[kt][3] = pack_h2(p2, p3); }
            }
        } else {
            #pragma unroll
            for (int nb = 0; nb < 8; nb++) {
                int c0 = j0 + nb*8 + 2*a;
                float p0 = (c0     < kma) ? exp2f(sf[nb][0]) : 0.f;
                float p1 = (c0 + 1 < kma) ? exp2f(sf[nb][1]) : 0.f;
                float p2 = (c0     < kmb) ? exp2f(sf[nb][2]) : 0.f;
                float p3 = (c0 + 1 < kmb) ? exp2f(sf[nb][3]) : 0.f;
                ps0 += p0 + p1;
                ps1 += p2 + p3;
                int kt = nb >> 1;
                if ((nb & 1) == 0) { pa[kt][0] = pack_h2(p0, p1); pa[kt][1] = pack_h2(p2, p3); }
                else               { pa[kt][2] = pack_h2(p0, p1); pa[kt][3] = pack_h2(p2, p3); }
            }
        }

        // ---- PV ----
        #pragma unroll
        for (int kt = 0; kt < 4; kt++) {
            #pragma unroll
            for (int db2 = 0; db2 < 8; db2++) {
                uint32_t b0, b1, b2, b3;
                uint32_t addr = vbase + (uint32_t)(db2*2048 + knp*128
                              + ((((kt << 1) | mb) ^ ksw) << 4));
                LDSM_X4(b0, b1, b2, b3, addr);
                MMA_F16(of[2*db2],     pa[kt], b0, b1);
                MMA_F16(of[2*db2 + 1], pa[kt], b2, b3);
            }
        }

        __syncthreads();
        int jn = j + 2;
        if (jn < nt) issue_tile(jn*BN, st);
        CP_COMMIT();
    }

    // ---- epilogue ----
    ps0 += __shfl_xor_sync(0xffffffffu, ps0, 1);
    ps0 += __shfl_xor_sync(0xffffffffu, ps0, 2);
    ps1 += __shfl_xor_sync(0xffffffffu, ps1, 1);
    ps1 += __shfl_xor_sync(0xffffffffu, ps1, 2);
    float li0 = 1.f / ps0, li1 = 1.f / ps1;

    if (kind == 0) {
        if (ra < SQ) {
            float* da = Out + (size_t)ra*(NHH*HDD) + h*HDD;
            #pragma unroll
            for (int n = 0; n < 16; n++)
                *(float2*)(da + n*8 + 2*a) = make_float2(of[n][0]*li0, of[n][1]*li0);
        }
        if (rb < SQ) {
            float* db = Out + (size_t)rb*(NHH*HDD) + h*HDD;
            #pragma unroll
            for (int n = 0; n < 16; n++)
                *(float2*)(db + n*8 + 2*a) = make_float2(of[n][2]*li1, of[n][3]*li1);
        }
    } else {
        // project with P: exchange partner half of each 4-group via lane^1
        const float* Pa = g_P[rca / TF];
        const float* Pb = g_P[rcb / TF];
        int r0 = (a & 1) * 2;   // this thread computes rows r0, r0+1 of P@v
        bool low = (a & 1) == 0;
        float* da = Out + (size_t)rca*(NHH*HDD) + h*HDD;
        float* db = Out + (size_t)rcb*(NHH*HDD) + h*HDD;
        #pragma unroll
        for (int n = 0; n < 16; n++) {
            float x0 = of[n][0]*li0, x1 = of[n][1]*li0;
            float x2 = of[n][2]*li1, x3 = of[n][3]*li1;
            float y0 = __shfl_xor_sync(0xffffffffu, x0, 1);
            float y1 = __shfl_xor_sync(0xffffffffu, x1, 1);
            float y2 = __shfl_xor_sync(0xffffffffu, x2, 1);
            float y3 = __shfl_xor_sync(0xffffffffu, x3, 1);
            float va0 = low ? x0 : y0, va1 = low ? x1 : y1;
            float va2 = low ? y0 : x0, va3 = low ? y1 : x1;
            float vb0 = low ? x2 : y2, vb1 = low ? x3 : y3;
            float vb2 = low ? y2 : x2, vb3 = low ? y3 : x3;
            if (ra < SQ) {
                float o0 = Pa[r0*4+0]*va0 + Pa[r0*4+1]*va1 + Pa[r0*4+2]*va2 + Pa[r0*4+3]*va3;
                float o1 = Pa[r0*4+4]*va0 + Pa[r0*4+5]*va1 + Pa[r0*4+6]*va2 + Pa[r0*4+7]*va3;
                *(float2*)(da + n*8 + 2*a) = make_float2(o0, o1);
            }
            if (rb < SQ) {
                float o0 = Pb[r0*4+0]*vb0 + Pb[r0*4+1]*vb1 + Pb[r0*4+2]*vb2 + Pb[r0*4+3]*vb3;
                float o1 = Pb[r0*4+4]*vb0 + Pb[r0*4+5]*vb1 + Pb[r0*4+6]*vb2 + Pb[r0*4+7]*vb3;
                *(float2*)(db + n*8 + 2*a) = make_float2(o0, o1);
            }
        }
    }
}

// ---------------- launch ----------------
extern "C" void kernel_launch(void* const* d_in, const int* in_sizes, int n_in,
                              void* d_out, int out_size) {
    const float* q    = (const float*)d_in[0];
    const float* k    = (const float*)d_in[1];
    const float* v    = (const float*)d_in[2];
    const float* cosb = (const float*)d_in[3];
    const float* sinb = (const float*)d_in[4];
    const float* vm   = (const float*)d_in[5];
    const float* Ks   = (const float*)d_in[6];
    float* out = (float*)d_out;

    const int smem_bytes = 2*STAGE_B;   // 65,536 B
    cudaFuncSetAttribute(attn_kernel, cudaFuncAttributeMaxDynamicSharedMemorySize, smem_bytes);

    mats_kernel<<<1, 32>>>(vm, Ks);
    preproc_kernel<<<(SQ*NHH*32 + 255)/256, 256>>>((const float4*)q, (const float4*)k, cosb, sinb);
    vtrans_kernel<<<dim3((SQ + 31)/32, HDD/32, NHH), dim3(32, 8)>>>(v);
    attn_kernel<<<dim3((SQ + BM - 1)/BM, NHH, 2), NTH, smem_bytes>>>(out);
}

// round 10
// speedup vs baseline: 10.6650x; 1.0001x over previous
#include <cuda_runtime.h>
#include <cuda_fp16.h>
#include <math.h>
#include <stdint.h>

#define SQ   2640
#define TF   880
#define NHH  12
#define HDD  128
#define NEL  (SQ*NHH*HDD)
#define SCALE 0.088388347648318447f
#define QSC   0.12751744729777468f   // SCALE * log2(e)

#define BM 64
#define BN 64
#define NTH 128
#define KTILE_B 16384          // 64 rows x 256 B (fp16)
#define VTILE_B 16384          // 128 d x 128 B
#define STAGE_B (KTILE_B + VTILE_B)

// ---------------- device scratch ----------------
__device__ __half g_qrh[NHH*SQ*HDD];        // rope Q [h][s][d]  (*QSC)
__device__ __half g_krh[NHH*SQ*HDD];        // rope K
__device__ __half g_qph[NHH*SQ*HDD];        // prope Q (*QSC)
__device__ __half g_kph[NHH*SQ*HDD];        // prope K
__device__ __half g_vrh[NHH*HDD*SQ + 64];   // V^T [h][d][s]
__device__ __half g_vph[NHH*HDD*SQ + 64];   // (Pinv V)^T
__device__ float  g_P  [3][16];
__device__ float  g_Pi [3][16];

// ---------------- helpers ----------------
__device__ __forceinline__ uint32_t smem_u32(const void* p) {
    return (uint32_t)__cvta_generic_to_shared(p);
}
__device__ __forceinline__ void cp_async16(uint32_t dst, const void* src) {
    asm volatile("cp.async.cg.shared.global [%0], [%1], 16;" :: "r"(dst), "l"(src));
}
#define CP_COMMIT() asm volatile("cp.async.commit_group;")

#define LDSM_X4(r0,r1,r2,r3,addr) \
    asm volatile("ldmatrix.sync.aligned.m8n8.x4.shared.b16 {%0,%1,%2,%3}, [%4];" \
        : "=r"(r0), "=r"(r1), "=r"(r2), "=r"(r3) : "r"(addr))

#define MMA_F16(D, A, b0, b1)                                                \
  asm volatile("mma.sync.aligned.m16n8k16.row.col.f32.f16.f16.f32 "          \
    "{%0,%1,%2,%3},{%4,%5,%6,%7},{%8,%9},{%0,%1,%2,%3};"                     \
    : "+f"((D)[0]), "+f"((D)[1]), "+f"((D)[2]), "+f"((D)[3])                 \
    : "r"((A)[0]), "r"((A)[1]), "r"((A)[2]), "r"((A)[3]), "r"(b0), "r"(b1))

__device__ __forceinline__ uint32_t pack_h2(float lo, float hi) {
    __half2 h = __floats2half2_rn(lo, hi);
    return *(uint32_t*)&h;
}

// ---------------- kernel 1: P, Pinv ----------------
__global__ void mats_kernel(const float* __restrict__ vm, const float* __restrict__ Ks) {
    int f = threadIdx.x;
    if (f >= 3) return;
    float P[16];
    for (int i = 0; i < 3; i++)
        for (int j = 0; j < 4; j++) {
            float s = 0.f;
            for (int k2 = 0; k2 < 3; k2++)
                s += Ks[f*9 + i*3 + k2] * vm[f*16 + k2*4 + j];
            P[i*4 + j] = s;
        }
    for (int j = 0; j < 4; j++) P[12 + j] = vm[f*16 + 12 + j];
    for (int i = 0; i < 16; i++) g_P[f][i] = P[i];

    double M[4][8];
    for (int i = 0; i < 4; i++)
        for (int j = 0; j < 4; j++) {
            M[i][j] = (double)P[i*4 + j];
            M[i][4 + j] = (i == j) ? 1.0 : 0.0;
        }
    for (int col = 0; col < 4; col++) {
        int piv = col; double best = fabs(M[col][col]);
        for (int r = col + 1; r < 4; r++)
            if (fabs(M[r][col]) > best) { best = fabs(M[r][col]); piv = r; }
        if (piv != col)
            for (int j = 0; j < 8; j++) { double t = M[col][j]; M[col][j] = M[piv][j]; M[piv][j] = t; }
        double inv = 1.0 / M[col][col];
        for (int j = 0; j < 8; j++) M[col][j] *= inv;
        for (int r = 0; r < 4; r++) {
            if (r == col) continue;
            double fm = M[r][col];
            for (int j = 0; j < 8; j++) M[r][j] -= fm * M[col][j];
        }
    }
    for (int i = 0; i < 4; i++)
        for (int j = 0; j < 4; j++)
            g_Pi[f][i*4 + j] = (float)M[i][4 + j];
}

// ---------------- kernel 2: RoPE + projective Q,K -> fp16 ----------------
__global__ void preproc_kernel(const float4* __restrict__ q, const float4* __restrict__ k,
                               const float* __restrict__ cosb, const float* __restrict__ sinb) {
    int t = blockIdx.x*blockDim.x + threadIdx.x;
    if (t >= SQ*NHH*32) return;
    int d4 = t & 31;
    int h  = (t >> 5) % NHH;
    int s  = t / (NHH*32);
    int f  = s / TF;

    float4 q4 = q[(s*NHH + h)*32 + d4];
    float4 k4 = k[(s*NHH + h)*32 + d4];
    float c0 = cosb[s*64 + 2*d4], c1 = cosb[s*64 + 2*d4 + 1];
    float s0 = sinb[s*64 + 2*d4], s1 = sinb[s*64 + 2*d4 + 1];

    float4 qr, kr;
    qr.x = (q4.x*c0 - q4.y*s0)*QSC; qr.y = (q4.y*c0 + q4.x*s0)*QSC;
    qr.z = (q4.z*c1 - q4.w*s1)*QSC; qr.w = (q4.w*c1 + q4.z*s1)*QSC;
    kr.x = k4.x*c0 - k4.y*s0;       kr.y = k4.y*c0 + k4.x*s0;
    kr.z = k4.z*c1 - k4.w*s1;       kr.w = k4.w*c1 + k4.z*s1;

    const float* P  = g_P[f];
    const float* Pi = g_Pi[f];
    float4 qp, kp;
    qp.x = (P[0] *q4.x + P[1] *q4.y + P[2] *q4.z + P[3] *q4.w)*QSC;
    qp.y = (P[4] *q4.x + P[5] *q4.y + P[6] *q4.z + P[7] *q4.w)*QSC;
    qp.z = (P[8] *q4.x + P[9] *q4.y + P[10]*q4.z + P[11]*q4.w)*QSC;
    qp.w = (P[12]*q4.x + P[13]*q4.y + P[14]*q4.z + P[15]*q4.w)*QSC;
    kp.x = Pi[0]*k4.x + Pi[4]*k4.y + Pi[8] *k4.z + Pi[12]*k4.w;  // Pinv^T @ k
    kp.y = Pi[1]*k4.x + Pi[5]*k4.y + Pi[9] *k4.z + Pi[13]*k4.w;
    kp.z = Pi[2]*k4.x + Pi[6]*k4.y + Pi[10]*k4.z + Pi[14]*k4.w;
    kp.w = Pi[3]*k4.x + Pi[7]*k4.y + Pi[11]*k4.z + Pi[15]*k4.w;

    size_t o = ((size_t)h*SQ + s)*HDD + d4*4;
    *(__half2*)(g_qrh + o)     = __floats2half2_rn(qr.x, qr.y);
    *(__half2*)(g_qrh + o + 2) = __floats2half2_rn(qr.z, qr.w);
    *(__half2*)(g_krh + o)     = __floats2half2_rn(kr.x, kr.y);
    *(__half2*)(g_krh + o + 2) = __floats2half2_rn(kr.z, kr.w);
    *(__half2*)(g_qph + o)     = __floats2half2_rn(qp.x, qp.y);
    *(__half2*)(g_qph + o + 2) = __floats2half2_rn(qp.z, qp.w);
    *(__half2*)(g_kph + o)     = __floats2half2_rn(kp.x, kp.y);
    *(__half2*)(g_kph + o + 2) = __floats2half2_rn(kp.z, kp.w);
}

// ---------------- kernel 3: V transpose + Pinv@V -> fp16 [h][d][s] ----------------
__global__ void vtrans_kernel(const float* __restrict__ v) {
    __shared__ float smv[32][33];
    int h  = blockIdx.z;
    int d0 = blockIdx.y * 32;
    int s0 = blockIdx.x * 32;
    int tx = threadIdx.x, ty = threadIdx.y;

    for (int i = ty; i < 32; i += 8) {
        int s = s0 + i;
        smv[i][tx] = (s < SQ) ? v[((size_t)s*NHH + h)*HDD + d0 + tx] : 0.f;
    }
    __syncthreads();

    int sw = s0 + tx;
    if (sw < SQ) {
        const float* Pi = g_Pi[sw / TF];
        for (int i = ty; i < 32; i += 8) {
            int d = d0 + i;
            int gb = i & ~3, a = i & 3;
            float vp = Pi[a*4+0]*smv[tx][gb]   + Pi[a*4+1]*smv[tx][gb+1]
                     + Pi[a*4+2]*smv[tx][gb+2] + Pi[a*4+3]*smv[tx][gb+3];
            g_vrh[((size_t)h*HDD + d)*SQ + sw] = __float2half_rn(smv[tx][i]);
            g_vph[((size_t)h*HDD + d)*SQ + sw] = __float2half_rn(vp);
        }
    }
}

// ---------------- kernel 4: fp16 flash attention, PV(j)⊗QK(j+1) interleaved ----------------
__global__ __launch_bounds__(NTH, 2) void attn_kernel(float* __restrict__ out) {
    extern __shared__ char smc[];
    uint32_t sb = smem_u32(smc);

    int kind = blockIdx.z, h = blockIdx.y;
    int row0 = (gridDim.x - 1 - blockIdx.x) * BM;   // longest blocks first
    int tid = threadIdx.x;
    int w = tid >> 5, lane = tid & 31, g = lane >> 2, a = lane & 3;
    int r8 = lane & 7, mhi = lane >> 3;
    int knp = ((mhi >> 1) << 3) + r8;   // row within matrix pair: 0..15
    int mb  = mhi & 1;                  // k-chunk parity
    int ksw = knp & 7;                  // swizzle key

    const __half* Q  = (kind ? g_qph : g_qrh) + (size_t)h*SQ*HDD;
    const __half* K  = (kind ? g_kph : g_krh) + (size_t)h*SQ*HDD;
    const __half* Vt = (kind ? g_vph : g_vrh) + (size_t)h*HDD*SQ;
    float* Out = out + (size_t)kind*NEL;

    int rw  = row0 + w*16;
    int ra  = rw + g, rb = rw + g + 8;
    int rca = min(ra, SQ-1), rcb = min(rb, SQ-1);
    int kma = (rca/TF + 1)*TF;
    int kmb = (rcb/TF + 1)*TF;
    int kmw = (min(rw, SQ-1)/TF + 1)*TF;   // warp-min mask bound
    int kend = (min(row0 + BM - 1, SQ-1)/TF + 1)*TF;
    int nt = (kend + BN - 1)/BN;

    // Q fragments (8 k16-steps x 4 regs)
    uint32_t qf[8][4];
    {
        const uint32_t* Qa = (const uint32_t*)(Q + (size_t)rca*HDD);
        const uint32_t* Qb = (const uint32_t*)(Q + (size_t)rcb*HDD);
        #pragma unroll
        for (int ks = 0; ks < 8; ks++) {
            qf[ks][0] = Qa[8*ks + a];
            qf[ks][1] = Qb[8*ks + a];
            qf[ks][2] = Qa[8*ks + a + 4];
            qf[ks][3] = Qb[8*ks + a + 4];
        }
    }

    float of[16][4];
    #pragma unroll
    for (int n = 0; n < 16; n++) { of[n][0]=0.f; of[n][1]=0.f; of[n][2]=0.f; of[n][3]=0.f; }
    float ps0 = 0.f, ps1 = 0.f;
    float sf[8][4];

    auto issue_tile = [&](int j0, int stg) {
        uint32_t kb = sb + (uint32_t)stg*STAGE_B;
        uint32_t vb = kb + KTILE_B;
        #pragma unroll
        for (int it = 0; it < 8; it++) {           // K: 64 rows x 16 chunks
            int idx = tid + it*NTH;
            int r = idx >> 4, c = idx & 15;
            cp_async16(kb + (uint32_t)(r*256 + ((c ^ (r & 7)) << 4)),
                       K + (size_t)min(j0 + r, SQ-1)*HDD + c*8);
        }
        #pragma unroll
        for (int it = 0; it < 8; it++) {           // V: 128 d x 8 chunks
            int idx = tid + it*NTH;
            int d = idx >> 3, c = idx & 7;
            cp_async16(vb + (uint32_t)(d*128 + ((c ^ (d & 7)) << 4)),
                       Vt + (size_t)d*SQ + j0 + c*8);
        }
    };

    issue_tile(0, 0);
    CP_COMMIT();
    issue_tile(BN, 1);
    CP_COMMIT();

    // ---- prologue: QK(0) ----
    asm volatile("cp.async.wait_group 1;");
    __syncthreads();
    #pragma unroll
    for (int n = 0; n < 8; n++) { sf[n][0]=0.f; sf[n][1]=0.f; sf[n][2]=0.f; sf[n][3]=0.f; }
    {
        uint32_t kbase = sb;
        #pragma unroll
        for (int i = 0; i < 32; i++) {
            int ks = i >> 2, nb2 = i & 3;
            uint32_t b0, b1, b2, b3;
            uint32_t addr = kbase + (uint32_t)(nb2*4096 + knp*256
                          + ((((ks << 1) | mb) ^ ksw) << 4));
            LDSM_X4(b0, b1, b2, b3, addr);
            MMA_F16(sf[2*nb2],     qf[ks], b0, b1);
            MMA_F16(sf[2*nb2 + 1], qf[ks], b2, b3);
        }
    }

    int st = 0;
    for (int j = 0; j < nt; j++, st ^= 1) {
        // ---- softmax(j) (no-max, exp2), pack P fragments ----
        int j0 = j*BN;
        uint32_t pa[4][4];
        if (j0 + BN <= kmw) {                 // interior tile: no masking
            #pragma unroll
            for (int nb = 0; nb < 8; nb++) {
                float p0 = exp2f(sf[nb][0]);
                float p1 = exp2f(sf[nb][1]);
                float p2 = exp2f(sf[nb][2]);
                float p3 = exp2f(sf[nb][3]);
                ps0 += p0 + p1;
                ps1 += p2 + p3;
                int kt = nb >> 1;
                if ((nb & 1) == 0) { pa[kt][0] = pack_h2(p0, p1); pa[kt][1] = pack_h2(p2, p3); }
                else               { pa[kt][2] = pack_h2(p0, p1); pa[kt][3] = pack_h2(p2, p3); }
            }
        } else {
            #pragma unroll
            for (int nb = 0; nb < 8; nb++) {
                int c0 = j0 + nb*8 + 2*a;
                float p0 = (c0     < kma) ? exp2f(sf[nb][0]) : 0.f;
                float p1 = (c0 + 1 < kma) ? exp2f(sf[nb][1]) : 0.f;
                float p2 = (c0     < kmb) ? exp2f(sf[nb][2]) : 0.f;
                float p3 = (c0 + 1 < kmb) ? exp2f(sf[nb][3]) : 0.f;
                ps0 += p0 + p1;
                ps1 += p2 + p3;
                int kt = nb >> 1;
                if ((nb & 1) == 0) { pa[kt][0] = pack_h2(p0, p1); pa[kt][1] = pack_h2(p2, p3); }
                else               { pa[kt][2] = pack_h2(p0, p1); pa[kt][3] = pack_h2(p2, p3); }
            }
        }

        // ---- tile j+1 visible to all ----
        asm volatile("cp.async.wait_group 0;");
        __syncthreads();

        bool doqk = (j + 1 < nt);
        if (doqk) {
            #pragma unroll
            for (int n = 0; n < 8; n++) { sf[n][0]=0.f; sf[n][1]=0.f; sf[n][2]=0.f; sf[n][3]=0.f; }
        }
        uint32_t vbase = sb + (uint32_t)st*STAGE_B + KTILE_B;        // V(j)
        uint32_t kbase = sb + (uint32_t)((st ^ 1))*STAGE_B;          // K(j+1)

        // ---- interleaved PV(j) ⊗ QK(j+1): two independent dep-chains ----
        #pragma unroll
        for (int i = 0; i < 32; i++) {
            {
                int kt = i >> 3, db2 = i & 7;
                uint32_t b0, b1, b2, b3;
                uint32_t addr = vbase + (uint32_t)(db2*2048 + knp*128
                              + ((((kt << 1) | mb) ^ ksw) << 4));
                LDSM_X4(b0, b1, b2, b3, addr);
                MMA_F16(of[2*db2],     pa[kt], b0, b1);
                MMA_F16(of[2*db2 + 1], pa[kt], b2, b3);
            }
            if (doqk) {
                int ks = i >> 2, nb2 = i & 3;
                uint32_t c0, c1, c2, c3;
                uint32_t addr = kbase + (uint32_t)(nb2*4096 + knp*256
                              + ((((ks << 1) | mb) ^ ksw) << 4));
                LDSM_X4(c0, c1, c2, c3, addr);
                MMA_F16(sf[2*nb2],     qf[ks], c0, c1);
                MMA_F16(sf[2*nb2 + 1], qf[ks], c2, c3);
            }
        }

        __syncthreads();              // stage st fully consumed
        int jn = j + 2;
        if (jn < nt) issue_tile(jn*BN, st);
        CP_COMMIT();
    }

    // ---- epilogue ----
    ps0 += __shfl_xor_sync(0xffffffffu, ps0, 1);
    ps0 += __shfl_xor_sync(0xffffffffu, ps0, 2);
    ps1 += __shfl_xor_sync(0xffffffffu, ps1, 1);
    ps1 += __shfl_xor_sync(0xffffffffu, ps1, 2);
    float li0 = 1.f / ps0, li1 = 1.f / ps1;

    if (kind == 0) {
        if (ra < SQ) {
            float* da = Out + (size_t)ra*(NHH*HDD) + h*HDD;
            #pragma unroll
            for (int n = 0; n < 16; n++)
                *(float2*)(da + n*8 + 2*a) = make_float2(of[n][0]*li0, of[n][1]*li0);
        }
        if (rb < SQ) {
            float* db = Out + (size_t)rb*(NHH*HDD) + h*HDD;
            #pragma unroll
            for (int n = 0; n < 16; n++)
                *(float2*)(db + n*8 + 2*a) = make_float2(of[n][2]*li1, of[n][3]*li1);
        }
    } else {
        // project with P: exchange partner half of each 4-group via lane^1
        const float* Pa = g_P[rca / TF];
        const float* Pb = g_P[rcb / TF];
        int r0 = (a & 1) * 2;
        bool low = (a & 1) == 0;
        float* da = Out + (size_t)rca*(NHH*HDD) + h*HDD;
        float* db = Out + (size_t)rcb*(NHH*HDD) + h*HDD;
        #pragma unroll
        for (int n = 0; n < 16; n++) {
            float x0 = of[n][0]*li0, x1 = of[n][1]*li0;
            float x2 = of[n][2]*li1, x3 = of[n][3]*li1;
            float y0 = __shfl_xor_sync(0xffffffffu, x0, 1);
            float y1 = __shfl_xor_sync(0xffffffffu, x1, 1);
            float y2 = __shfl_xor_sync(0xffffffffu, x2, 1);
            float y3 = __shfl_xor_sync(0xffffffffu, x3, 1);
            float va0 = low ? x0 : y0, va1 = low ? x1 : y1;
            float va2 = low ? y0 : x0, va3 = low ? y1 : x1;
            float vb0 = low ? x2 : y2, vb1 = low ? x3 : y3;
            float vb2 = low ? y2 : x2, vb3 = low ? y3 : x3;
            if (ra < SQ) {
                float o0 = Pa[r0*4+0]*va0 + Pa[r0*4+1]*va1 + Pa[r0*4+2]*va2 + Pa[r0*4+3]*va3;
                float o1 = Pa[r0*4+4]*va0 + Pa[r0*4+5]*va1 + Pa[r0*4+6]*va2 + Pa[r0*4+7]*va3;
                *(float2*)(da + n*8 + 2*a) = make_float2(o0, o1);
            }
            if (rb < SQ) {
                float o0 = Pb[r0*4+0]*vb0 + Pb[r0*4+1]*vb1 + Pb[r0*4+2]*vb2 + Pb[r0*4+3]*vb3;
                float o1 = Pb[r0*4+4]*vb0 + Pb[r0*4+5]*vb1 + Pb[r0*4+6]*vb2 + Pb[r0*4+7]*vb3;
                *(float2*)(db + n*8 + 2*a) = make_float2(o0, o1);
            }
        }
    }
}

// ---------------- launch ----------------
extern "C" void kernel_launch(void* const* d_in, const int* in_sizes, int n_in,
                              void* d_out, int out_size) {
    const float* q    = (const float*)d_in[0];
    const float* k    = (const float*)d_in[1];
    const float* v    = (const float*)d_in[2];
    const float* cosb = (const float*)d_in[3];
    const float* sinb = (const float*)d_in[4];
    const float* vm   = (const float*)d_in[5];
    const float* Ks   = (const float*)d_in[6];
    float* out = (float*)d_out;

    const int smem_bytes = 2*STAGE_B;   // 65,536 B
    cudaFuncSetAttribute(attn_kernel, cudaFuncAttributeMaxDynamicSharedMemorySize, smem_bytes);

    mats_kernel<<<1, 32>>>(vm, Ks);
    preproc_kernel<<<(SQ*NHH*32 + 255)/256, 256>>>((const float4*)q, (const float4*)k, cosb, sinb);
    vtrans_kernel<<<dim3((SQ + 31)/32, HDD/32, NHH), dim3(32, 8)>>>(v);
    attn_kernel<<<dim3((SQ + BM - 1)/BM, NHH, 2), NTH, smem_bytes>>>(out);
}

// round 11
// speedup vs baseline: 10.7483x; 1.0078x over previous
#include <cuda_runtime.h>
#include <cuda_fp16.h>
#include <math.h>
#include <stdint.h>

#define SQ   2640
#define TF   880
#define NHH  12
#define HDD  128
#define NEL  (SQ*NHH*HDD)
#define SCALE 0.088388347648318447f
#define QSC   0.12751744729777468f   // SCALE * log2(e)

#define BM 64
#define BN 64
#define NTH 128
#define KTILE_B 16384          // 64 rows x 256 B (fp16)
#define VTILE_B 16384          // 128 d x 128 B
#define STAGE_B (KTILE_B + VTILE_B)
#define NSTG 3

// ---------------- device scratch ----------------
__device__ __half g_qrh[NHH*SQ*HDD];        // rope Q [h][s][d]  (*QSC)
__device__ __half g_krh[NHH*SQ*HDD];        // rope K
__device__ __half g_qph[NHH*SQ*HDD];        // prope Q (*QSC)
__device__ __half g_kph[NHH*SQ*HDD];        // prope K
__device__ __half g_vrh[NHH*HDD*SQ + 64];   // V^T [h][d][s]
__device__ __half g_vph[NHH*HDD*SQ + 64];   // (Pinv V)^T
__device__ float  g_P  [3][16];
__device__ float  g_Pi [3][16];

// ---------------- helpers ----------------
__device__ __forceinline__ uint32_t smem_u32(const void* p) {
    return (uint32_t)__cvta_generic_to_shared(p);
}
__device__ __forceinline__ void cp_async16(uint32_t dst, const void* src) {
    asm volatile("cp.async.cg.shared.global [%0], [%1], 16;" :: "r"(dst), "l"(src));
}
#define CP_COMMIT() asm volatile("cp.async.commit_group;")

#define LDSM_X4(r0,r1,r2,r3,addr) \
    asm volatile("ldmatrix.sync.aligned.m8n8.x4.shared.b16 {%0,%1,%2,%3}, [%4];" \
        : "=r"(r0), "=r"(r1), "=r"(r2), "=r"(r3) : "r"(addr))

#define MMA_F16(D, A, b0, b1)                                                \
  asm volatile("mma.sync.aligned.m16n8k16.row.col.f32.f16.f16.f32 "          \
    "{%0,%1,%2,%3},{%4,%5,%6,%7},{%8,%9},{%0,%1,%2,%3};"                     \
    : "+f"((D)[0]), "+f"((D)[1]), "+f"((D)[2]), "+f"((D)[3])                 \
    : "r"((A)[0]), "r"((A)[1]), "r"((A)[2]), "r"((A)[3]), "r"(b0), "r"(b1))

__device__ __forceinline__ uint32_t pack_h2(float lo, float hi) {
    __half2 h = __floats2half2_rn(lo, hi);
    return *(uint32_t*)&h;
}

// ---------------- kernel 1: P, Pinv ----------------
__global__ void mats_kernel(const float* __restrict__ vm, const float* __restrict__ Ks) {
    int f = threadIdx.x;
    if (f >= 3) return;
    float P[16];
    for (int i = 0; i < 3; i++)
        for (int j = 0; j < 4; j++) {
            float s = 0.f;
            for (int k2 = 0; k2 < 3; k2++)
                s += Ks[f*9 + i*3 + k2] * vm[f*16 + k2*4 + j];
            P[i*4 + j] = s;
        }
    for (int j = 0; j < 4; j++) P[12 + j] = vm[f*16 + 12 + j];
    for (int i = 0; i < 16; i++) g_P[f][i] = P[i];

    double M[4][8];
    for (int i = 0; i < 4; i++)
        for (int j = 0; j < 4; j++) {
            M[i][j] = (double)P[i*4 + j];
            M[i][4 + j] = (i == j) ? 1.0 : 0.0;
        }
    for (int col = 0; col < 4; col++) {
        int piv = col; double best = fabs(M[col][col]);
        for (int r = col + 1; r < 4; r++)
            if (fabs(M[r][col]) > best) { best = fabs(M[r][col]); piv = r; }
        if (piv != col)
            for (int j = 0; j < 8; j++) { double t = M[col][j]; M[col][j] = M[piv][j]; M[piv][j] = t; }
        double inv = 1.0 / M[col][col];
        for (int j = 0; j < 8; j++) M[col][j] *= inv;
        for (int r = 0; r < 4; r++) {
            if (r == col) continue;
            double fm = M[r][col];
            for (int j = 0; j < 8; j++) M[r][j] -= fm * M[col][j];
        }
    }
    for (int i = 0; i < 4; i++)
        for (int j = 0; j < 4; j++)
            g_Pi[f][i*4 + j] = (float)M[i][4 + j];
}

// ---------------- kernel 2: RoPE + projective Q,K -> fp16 ----------------
__global__ void preproc_kernel(const float4* __restrict__ q, const float4* __restrict__ k,
                               const float* __restrict__ cosb, const float* __restrict__ sinb) {
    int t = blockIdx.x*blockDim.x + threadIdx.x;
    if (t >= SQ*NHH*32) return;
    int d4 = t & 31;
    int h  = (t >> 5) % NHH;
    int s  = t / (NHH*32);
    int f  = s / TF;

    float4 q4 = q[(s*NHH + h)*32 + d4];
    float4 k4 = k[(s*NHH + h)*32 + d4];
    float c0 = cosb[s*64 + 2*d4], c1 = cosb[s*64 + 2*d4 + 1];
    float s0 = sinb[s*64 + 2*d4], s1 = sinb[s*64 + 2*d4 + 1];

    float4 qr, kr;
    qr.x = (q4.x*c0 - q4.y*s0)*QSC; qr.y = (q4.y*c0 + q4.x*s0)*QSC;
    qr.z = (q4.z*c1 - q4.w*s1)*QSC; qr.w = (q4.w*c1 + q4.z*s1)*QSC;
    kr.x = k4.x*c0 - k4.y*s0;       kr.y = k4.y*c0 + k4.x*s0;
    kr.z = k4.z*c1 - k4.w*s1;       kr.w = k4.w*c1 + k4.z*s1;

    const float* P  = g_P[f];
    const float* Pi = g_Pi[f];
    float4 qp, kp;
    qp.x = (P[0] *q4.x + P[1] *q4.y + P[2] *q4.z + P[3] *q4.w)*QSC;
    qp.y = (P[4] *q4.x + P[5] *q4.y + P[6] *q4.z + P[7] *q4.w)*QSC;
    qp.z = (P[8] *q4.x + P[9] *q4.y + P[10]*q4.z + P[11]*q4.w)*QSC;
    qp.w = (P[12]*q4.x + P[13]*q4.y + P[14]*q4.z + P[15]*q4.w)*QSC;
    kp.x = Pi[0]*k4.x + Pi[4]*k4.y + Pi[8] *k4.z + Pi[12]*k4.w;  // Pinv^T @ k
    kp.y = Pi[1]*k4.x + Pi[5]*k4.y + Pi[9] *k4.z + Pi[13]*k4.w;
    kp.z = Pi[2]*k4.x + Pi[6]*k4.y + Pi[10]*k4.z + Pi[14]*k4.w;
    kp.w = Pi[3]*k4.x + Pi[7]*k4.y + Pi[11]*k4.z + Pi[15]*k4.w;

    size_t o = ((size_t)h*SQ + s)*HDD + d4*4;
    *(__half2*)(g_qrh + o)     = __floats2half2_rn(qr.x, qr.y);
    *(__half2*)(g_qrh + o + 2) = __floats2half2_rn(qr.z, qr.w);
    *(__half2*)(g_krh + o)     = __floats2half2_rn(kr.x, kr.y);
    *(__half2*)(g_krh + o + 2) = __floats2half2_rn(kr.z, kr.w);
    *(__half2*)(g_qph + o)     = __floats2half2_rn(qp.x, qp.y);
    *(__half2*)(g_qph + o + 2) = __floats2half2_rn(qp.z, qp.w);
    *(__half2*)(g_kph + o)     = __floats2half2_rn(kp.x, kp.y);
    *(__half2*)(g_kph + o + 2) = __floats2half2_rn(kp.z, kp.w);
}

// ---------------- kernel 3: V transpose + Pinv@V -> fp16 [h][d][s] ----------------
__global__ void vtrans_kernel(const float* __restrict__ v) {
    __shared__ float smv[32][33];
    int h  = blockIdx.z;
    int d0 = blockIdx.y * 32;
    int s0 = blockIdx.x * 32;
    int tx = threadIdx.x, ty = threadIdx.y;

    for (int i = ty; i < 32; i += 8) {
        int s = s0 + i;
        smv[i][tx] = (s < SQ) ? v[((size_t)s*NHH + h)*HDD + d0 + tx] : 0.f;
    }
    __syncthreads();

    int sw = s0 + tx;
    if (sw < SQ) {
        const float* Pi = g_Pi[sw / TF];
        for (int i = ty; i < 32; i += 8) {
            int d = d0 + i;
            int gb = i & ~3, a = i & 3;
            float vp = Pi[a*4+0]*smv[tx][gb]   + Pi[a*4+1]*smv[tx][gb+1]
                     + Pi[a*4+2]*smv[tx][gb+2] + Pi[a*4+3]*smv[tx][gb+3];
            g_vrh[((size_t)h*HDD + d)*SQ + sw] = __float2half_rn(smv[tx][i]);
            g_vph[((size_t)h*HDD + d)*SQ + sw] = __float2half_rn(vp);
        }
    }
}

// ---------------- kernel 4: fp16 flash attention, 3-stage ring, 1 barrier/tile ----------------
__global__ __launch_bounds__(NTH, 2) void attn_kernel(float* __restrict__ out) {
    extern __shared__ char smc[];
    uint32_t sb = smem_u32(smc);

    int kind = blockIdx.z, h = blockIdx.y;
    int row0 = (gridDim.x - 1 - blockIdx.x) * BM;   // longest blocks first
    int tid = threadIdx.x;
    int w = tid >> 5, lane = tid & 31, g = lane >> 2, a = lane & 3;
    int r8 = lane & 7, mhi = lane >> 3;
    int knp = ((mhi >> 1) << 3) + r8;   // row within matrix pair: 0..15
    int mb  = mhi & 1;                  // k-chunk parity
    int ksw = knp & 7;                  // swizzle key

    const __half* Q  = (kind ? g_qph : g_qrh) + (size_t)h*SQ*HDD;
    const __half* K  = (kind ? g_kph : g_krh) + (size_t)h*SQ*HDD;
    const __half* Vt = (kind ? g_vph : g_vrh) + (size_t)h*HDD*SQ;
    float* Out = out + (size_t)kind*NEL;

    int rw  = row0 + w*16;
    int ra  = rw + g, rb = rw + g + 8;
    int rca = min(ra, SQ-1), rcb = min(rb, SQ-1);
    int kma = (rca/TF + 1)*TF;
    int kmb = (rcb/TF + 1)*TF;
    int kmw = (min(rw, SQ-1)/TF + 1)*TF;   // warp-min mask bound
    int kend = (min(row0 + BM - 1, SQ-1)/TF + 1)*TF;
    int nt = (kend + BN - 1)/BN;

    // Q fragments (8 k16-steps x 4 regs)
    uint32_t qf[8][4];
    {
        const uint32_t* Qa = (const uint32_t*)(Q + (size_t)rca*HDD);
        const uint32_t* Qb = (const uint32_t*)(Q + (size_t)rcb*HDD);
        #pragma unroll
        for (int ks = 0; ks < 8; ks++) {
            qf[ks][0] = Qa[8*ks + a];
            qf[ks][1] = Qb[8*ks + a];
            qf[ks][2] = Qa[8*ks + a + 4];
            qf[ks][3] = Qb[8*ks + a + 4];
        }
    }

    float of[16][4];
    #pragma unroll
    for (int n = 0; n < 16; n++) { of[n][0]=0.f; of[n][1]=0.f; of[n][2]=0.f; of[n][3]=0.f; }
    float ps0 = 0.f, ps1 = 0.f;
    float sf[8][4];

    auto issue_tile = [&](int j0, int stg) {
        uint32_t kb = sb + (uint32_t)stg*STAGE_B;
        uint32_t vb = kb + KTILE_B;
        #pragma unroll
        for (int it = 0; it < 8; it++) {           // K: 64 rows x 16 chunks
            int idx = tid + it*NTH;
            int r = idx >> 4, c = idx & 15;
            cp_async16(kb + (uint32_t)(r*256 + ((c ^ (r & 7)) << 4)),
                       K + (size_t)min(j0 + r, SQ-1)*HDD + c*8);
        }
        #pragma unroll
        for (int it = 0; it < 8; it++) {           // V: 128 d x 8 chunks
            int idx = tid + it*NTH;
            int d = idx >> 3, c = idx & 7;
            cp_async16(vb + (uint32_t)(d*128 + ((c ^ (d & 7)) << 4)),
                       Vt + (size_t)d*SQ + min(j0 + c*8, SQ-8));
        }
        CP_COMMIT();
    };

    issue_tile(0, 0);
    issue_tile(BN, 1);

    // ---- prologue: QK(0) from stage 0 ----
    asm volatile("cp.async.wait_group 1;");
    __syncthreads();
    #pragma unroll
    for (int n = 0; n < 8; n++) { sf[n][0]=0.f; sf[n][1]=0.f; sf[n][2]=0.f; sf[n][3]=0.f; }
    {
        uint32_t kbase = sb;
        #pragma unroll
        for (int i = 0; i < 32; i++) {
            int ks = i >> 2, nb2 = i & 3;
            uint32_t b0, b1, b2, b3;
            uint32_t addr = kbase + (uint32_t)(nb2*4096 + knp*256
                          + ((((ks << 1) | mb) ^ ksw) << 4));
            LDSM_X4(b0, b1, b2, b3, addr);
            MMA_F16(sf[2*nb2],     qf[ks], b0, b1);
            MMA_F16(sf[2*nb2 + 1], qf[ks], b2, b3);
        }
    }

    int stv = 0;   // stage of tile j (V side); K(j+1) is stage (stv+1)%3
    for (int j = 0; j < nt; j++) {
        // ---- softmax(j) (no-max, exp2), pack P fragments ----
        int j0 = j*BN;
        uint32_t pa[4][4];
        if (j0 + BN <= kmw) {                 // interior tile: no masking
            #pragma unroll
            for (int nb = 0; nb < 8; nb++) {
                float p0 = exp2f(sf[nb][0]);
                float p1 = exp2f(sf[nb][1]);
                float p2 = exp2f(sf[nb][2]);
                float p3 = exp2f(sf[nb][3]);
                ps0 += p0 + p1;
                ps1 += p2 + p3;
                int kt = nb >> 1;
                if ((nb & 1) == 0) { pa[kt][0] = pack_h2(p0, p1); pa[kt][1] = pack_h2(p2, p3); }
                else               { pa[kt][2] = pack_h2(p0, p1); pa[kt][3] = pack_h2(p2, p3); }
            }
        } else {
            #pragma unroll
            for (int nb = 0; nb < 8; nb++) {
                int c0 = j0 + nb*8 + 2*a;
                float p0 = (c0     < kma) ? exp2f(sf[nb][0]) : 0.f;
                float p1 = (c0 + 1 < kma) ? exp2f(sf[nb][1]) : 0.f;
                float p2 = (c0     < kmb) ? exp2f(sf[nb][2]) : 0.f;
                float p3 = (c0 + 1 < kmb) ? exp2f(sf[nb][3]) : 0.f;
                ps0 += p0 + p1;
                ps1 += p2 + p3;
                int kt = nb >> 1;
                if ((nb & 1) == 0) { pa[kt][0] = pack_h2(p0, p1); pa[kt][1] = pack_h2(p2, p3); }
                else               { pa[kt][2] = pack_h2(p0, p1); pa[kt][3] = pack_h2(p2, p3); }
            }
        }

        // ---- tile j+1 arrived (issued one full iteration ago); ONE barrier ----
        asm volatile("cp.async.wait_group 0;");
        __syncthreads();

        // ---- prefetch tile j+2 into the idle ring slot (stv+2)%3 ----
        // slot (stv+2)%3 was last read in iteration j-1; all warps passed the barrier.
        int jn = j + 2;
        if (jn < nt) {
            int stn = stv + 2; if (stn >= NSTG) stn -= NSTG;
            issue_tile(jn*BN, stn);
        }

        bool doqk = (j + 1 < nt);
        if (doqk) {
            #pragma unroll
            for (int n = 0; n < 8; n++) { sf[n][0]=0.f; sf[n][1]=0.f; sf[n][2]=0.f; sf[n][3]=0.f; }
        }
        int stk = stv + 1; if (stk >= NSTG) stk -= NSTG;
        uint32_t vbase = sb + (uint32_t)stv*STAGE_B + KTILE_B;        // V(j)
        uint32_t kbase = sb + (uint32_t)stk*STAGE_B;                  // K(j+1)

        // ---- interleaved PV(j) ⊗ QK(j+1) ----
        #pragma unroll
        for (int i = 0; i < 32; i++) {
            {
                int kt = i >> 3, db2 = i & 7;
                uint32_t b0, b1, b2, b3;
                uint32_t addr = vbase + (uint32_t)(db2*2048 + knp*128
                              + ((((kt << 1) | mb) ^ ksw) << 4));
                LDSM_X4(b0, b1, b2, b3, addr);
                MMA_F16(of[2*db2],     pa[kt], b0, b1);
                MMA_F16(of[2*db2 + 1], pa[kt], b2, b3);
            }
            if (doqk) {
                int ks = i >> 2, nb2 = i & 3;
                uint32_t c0, c1, c2, c3;
                uint32_t addr = kbase + (uint32_t)(nb2*4096 + knp*256
                              + ((((ks << 1) | mb) ^ ksw) << 4));
                LDSM_X4(c0, c1, c2, c3, addr);
                MMA_F16(sf[2*nb2],     qf[ks], c0, c1);
                MMA_F16(sf[2*nb2 + 1], qf[ks], c2, c3);
            }
        }

        stv = stk;
    }

    // ---- epilogue ----
    ps0 += __shfl_xor_sync(0xffffffffu, ps0, 1);
    ps0 += __shfl_xor_sync(0xffffffffu, ps0, 2);
    ps1 += __shfl_xor_sync(0xffffffffu, ps1, 1);
    ps1 += __shfl_xor_sync(0xffffffffu, ps1, 2);
    float li0 = 1.f / ps0, li1 = 1.f / ps1;

    if (kind == 0) {
        if (ra < SQ) {
            float* da = Out + (size_t)ra*(NHH*HDD) + h*HDD;
            #pragma unroll
            for (int n = 0; n < 16; n++)
                *(float2*)(da + n*8 + 2*a) = make_float2(of[n][0]*li0, of[n][1]*li0);
        }
        if (rb < SQ) {
            float* db = Out + (size_t)rb*(NHH*HDD) + h*HDD;
            #pragma unroll
            for (int n = 0; n < 16; n++)
                *(float2*)(db + n*8 + 2*a) = make_float2(of[n][2]*li1, of[n][3]*li1);
        }
    } else {
        // project with P: exchange partner half of each 4-group via lane^1
        const float* Pa = g_P[rca / TF];
        const float* Pb = g_P[rcb / TF];
        int r0 = (a & 1) * 2;
        bool low = (a & 1) == 0;
        float* da = Out + (size_t)rca*(NHH*HDD) + h*HDD;
        float* db = Out + (size_t)rcb*(NHH*HDD) + h*HDD;
        #pragma unroll
        for (int n = 0; n < 16; n++) {
            float x0 = of[n][0]*li0, x1 = of[n][1]*li0;
            float x2 = of[n][2]*li1, x3 = of[n][3]*li1;
            float y0 = __shfl_xor_sync(0xffffffffu, x0, 1);
            float y1 = __shfl_xor_sync(0xffffffffu, x1, 1);
            float y2 = __shfl_xor_sync(0xffffffffu, x2, 1);
            float y3 = __shfl_xor_sync(0xffffffffu, x3, 1);
            float va0 = low ? x0 : y0, va1 = low ? x1 : y1;
            float va2 = low ? y0 : x0, va3 = low ? y1 : x1;
            float vb0 = low ? x2 : y2, vb1 = low ? x3 : y3;
            float vb2 = low ? y2 : x2, vb3 = low ? y3 : x3;
            if (ra < SQ) {
                float o0 = Pa[r0*4+0]*va0 + Pa[r0*4+1]*va1 + Pa[r0*4+2]*va2 + Pa[r0*4+3]*va3;
                float o1 = Pa[r0*4+4]*va0 + Pa[r0*4+5]*va1 + Pa[r0*4+6]*va2 + Pa[r0*4+7]*va3;
                *(float2*)(da + n*8 + 2*a) = make_float2(o0, o1);
            }
            if (rb < SQ) {
                float o0 = Pb[r0*4+0]*vb0 + Pb[r0*4+1]*vb1 + Pb[r0*4+2]*vb2 + Pb[r0*4+3]*vb3;
                float o1 = Pb[r0*4+4]*vb0 + Pb[r0*4+5]*vb1 + Pb[r0*4+6]*vb2 + Pb[r0*4+7]*vb3;
                *(float2*)(db + n*8 + 2*a) = make_float2(o0, o1);
            }
        }
    }
}

// ---------------- launch ----------------
extern "C" void kernel_launch(void* const* d_in, const int* in_sizes, int n_in,
                              void* d_out, int out_size) {
    const float* q    = (const float*)d_in[0];
    const float* k    = (const float*)d_in[1];
    const float* v    = (const float*)d_in[2];
    const float* cosb = (const float*)d_in[3];
    const float* sinb = (const float*)d_in[4];
    const float* vm   = (const float*)d_in[5];
    const float* Ks   = (const float*)d_in[6];
    float* out = (float*)d_out;

    const int smem_bytes = NSTG*STAGE_B;   // 98,304 B
    cudaFuncSetAttribute(attn_kernel, cudaFuncAttributeMaxDynamicSharedMemorySize, smem_bytes);

    mats_kernel<<<1, 32>>>(vm, Ks);
    preproc_kernel<<<(SQ*NHH*32 + 255)/256, 256>>>((const float4*)q, (const float4*)k, cosb, sinb);
    vtrans_kernel<<<dim3((SQ + 31)/32, HDD/32, NHH), dim3(32, 8)>>>(v);
    attn_kernel<<<dim3((SQ + BM - 1)/BM, NHH, 2), NTH, smem_bytes>>>(out);
}